// round 2
// baseline (speedup 1.0000x reference)
#include <cuda_runtime.h>

#define N_NODES 50000
#define N_EDGES 625000
#define HID 128
#define NT 4

// ---------------- scratch (device globals; no allocation allowed) ----------------
__device__ float g_agg[N_NODES * HID];           // 25.6 MB  scatter target (fits L2)
__device__ float g_Wt[NT * HID * HID];           // edge_W transposed: Wt[t][k][j] = W[t][j][k]
__device__ float g_WihT[3 * HID * HID];
__device__ float g_WhhT[3 * HID * HID];
__device__ float g_gi[(size_t)N_NODES * 3 * HID];
__device__ float g_gh[(size_t)N_NODES * 3 * HID];
__device__ int   g_bucket[NT * N_EDGES];         // edge ids compacted by type
__device__ int   g_cnt[NT];
__device__ int   g_is64;                         // 1 if edge_index/edge_type are int64

// Uniform-branch index load: works for int32 or int64 storage.
__device__ __forceinline__ int load_idx(const void* p, int i, int is64) {
    if (is64) return (int)((const long long*)p)[i];
    return ((const int*)p)[i];
}

// ---------------- dtype detect (single thread) ----------------
// If storage is int64, values < 2^31 mean every odd 32-bit word is 0.
__global__ void detect_kernel(const int* __restrict__ ei_as_i32) {
    int ok = 1;
    for (int i = 0; i < 64; i++)
        if (ei_as_i32[2 * i + 1] != 0) ok = 0;
    g_is64 = ok;
}

// ---------------- prep: zero agg/counters, transpose weights ----------------
__global__ void prep_kernel(const float* __restrict__ eW,
                            const float* __restrict__ wih,
                            const float* __restrict__ whh) {
    int i = blockIdx.x * blockDim.x + threadIdx.x;
    if (i < N_NODES * HID) g_agg[i] = 0.0f;
    if (i < NT * HID * HID) {
        int t = i >> 14, r = i & 16383, k = r >> 7, j = r & 127;
        g_Wt[i] = eW[(t << 14) + (j << 7) + k];
    }
    if (i < 3 * HID * HID) {
        int g = i >> 14, r = i & 16383, k = r >> 7, j = r & 127;
        g_WihT[i] = wih[((g << 7) + j) * HID + k];
        g_WhhT[i] = whh[((g << 7) + j) * HID + k];
    }
    if (i < NT) g_cnt[i] = 0;
}

// ---------------- bucket edges by type ----------------
__global__ void bucket_kernel(const void* __restrict__ etype) {
    int e = blockIdx.x * blockDim.x + threadIdx.x;
    if (e < N_EDGES) {
        int is64 = g_is64;
        int t = load_idx(etype, e, is64) & (NT - 1);
        int pos = atomicAdd(&g_cnt[t], 1);
        g_bucket[t * N_EDGES + pos] = e;
    }
}

// ---------------- edge message GEMM + scatter-add ----------------
// blockIdx.y = edge type. 256 threads = 8 warps. Each warp processes tiles of
// 8 same-type edges; W[t]^T lives in SMEM (64KB); x rows staged in SMEM.
// Lane l owns output dims [4l, 4l+4).
__global__ void edge_gemm_kernel(const float* __restrict__ ns,
                                 const void* __restrict__ eidx,
                                 const float* __restrict__ eb) {
    extern __shared__ float smem[];
    float* sW = smem;                // [128][128]
    float* sx = smem + HID * HID;    // [8 warps][8 edges][128]

    int t = blockIdx.y;
    int cnt = g_cnt[t];
    int is64 = g_is64;
    for (int i = threadIdx.x; i < HID * HID; i += blockDim.x)
        sW[i] = g_Wt[t * HID * HID + i];

    int lane = threadIdx.x & 31;
    int warp = threadIdx.x >> 5;
    float4 b4 = *(const float4*)(eb + t * HID + 4 * lane);
    __syncthreads();

    float* sxw = sx + warp * 8 * HID;
    int tiles = (cnt + 7) >> 3;
    int w  = blockIdx.x * (blockDim.x >> 5) + warp;
    int ws = gridDim.x * (blockDim.x >> 5);

    for (int tile = w; tile < tiles; tile += ws) {
        int base = tile * 8;
        int m = min(8, cnt - base);
        int src = 0, dst = 0;
        if (lane < m) {
            int e = g_bucket[t * N_EDGES + base + lane];
            src = load_idx(eidx, e, is64);
            dst = load_idx(eidx, N_EDGES + e, is64);
        }
        // gather x_src rows (zero-fill tail so compute is unconditional)
        #pragma unroll
        for (int e = 0; e < 8; e++) {
            int s = __shfl_sync(0xffffffffu, src, e);
            float4 v = make_float4(0.f, 0.f, 0.f, 0.f);
            if (e < m) v = *(const float4*)(ns + (size_t)s * HID + 4 * lane);
            *(float4*)(sxw + e * HID + 4 * lane) = v;
        }
        __syncwarp();

        float4 acc[8] = {};
        #pragma unroll 2
        for (int k = 0; k < HID; k++) {
            float4 w4 = *(const float4*)(sW + k * HID + 4 * lane);
            #pragma unroll
            for (int e = 0; e < 8; e++) {
                float xk = sxw[e * HID + k];
                acc[e].x = fmaf(xk, w4.x, acc[e].x);
                acc[e].y = fmaf(xk, w4.y, acc[e].y);
                acc[e].z = fmaf(xk, w4.z, acc[e].z);
                acc[e].w = fmaf(xk, w4.w, acc[e].w);
            }
        }

        #pragma unroll
        for (int e = 0; e < 8; e++) {
            if (e < m) {
                int d = __shfl_sync(0xffffffffu, dst, e);
                float* ag = g_agg + (size_t)d * HID + 4 * lane;
                atomicAdd(ag + 0, acc[e].x + b4.x);
                atomicAdd(ag + 1, acc[e].y + b4.y);
                atomicAdd(ag + 2, acc[e].z + b4.z);
                atomicAdd(ag + 3, acc[e].w + b4.w);
            }
        }
        __syncwarp();
    }
}

// ---------------- GRU gate GEMMs ----------------
// blockIdx.y in [0,6): slices 0..2 = gi gates (in = agg, W = w_ih),
// 3..5 = gh gates (in = node_states, W = w_hh).
__global__ void gru_gemm_kernel(const float* __restrict__ ns,
                                const float* __restrict__ bih,
                                const float* __restrict__ bhh) {
    extern __shared__ float smem[];
    float* sW = smem;
    float* sx = smem + HID * HID;

    int s = blockIdx.y;
    int g = (s < 3) ? s : (s - 3);
    bool ih = (s < 3);
    const float* in   = ih ? g_agg : ns;
    const float* wt   = (ih ? g_WihT : g_WhhT) + g * HID * HID;
    const float* bias = (ih ? bih : bhh) + g * HID;
    float* out        = ih ? g_gi : g_gh;

    for (int i = threadIdx.x; i < HID * HID; i += blockDim.x) sW[i] = wt[i];

    int lane = threadIdx.x & 31;
    int warp = threadIdx.x >> 5;
    float4 b4 = *(const float4*)(bias + 4 * lane);
    __syncthreads();

    float* sxw = sx + warp * 8 * HID;
    int tiles = (N_NODES + 7) >> 3;
    int w  = blockIdx.x * (blockDim.x >> 5) + warp;
    int ws = gridDim.x * (blockDim.x >> 5);

    for (int tile = w; tile < tiles; tile += ws) {
        int base = tile * 8;
        int m = min(8, N_NODES - base);
        #pragma unroll
        for (int e = 0; e < 8; e++) {
            float4 v = make_float4(0.f, 0.f, 0.f, 0.f);
            if (e < m) v = *(const float4*)(in + (size_t)(base + e) * HID + 4 * lane);
            *(float4*)(sxw + e * HID + 4 * lane) = v;
        }
        __syncwarp();

        float4 acc[8] = {};
        #pragma unroll 2
        for (int k = 0; k < HID; k++) {
            float4 w4 = *(const float4*)(sW + k * HID + 4 * lane);
            #pragma unroll
            for (int e = 0; e < 8; e++) {
                float xk = sxw[e * HID + k];
                acc[e].x = fmaf(xk, w4.x, acc[e].x);
                acc[e].y = fmaf(xk, w4.y, acc[e].y);
                acc[e].z = fmaf(xk, w4.z, acc[e].z);
                acc[e].w = fmaf(xk, w4.w, acc[e].w);
            }
        }

        #pragma unroll
        for (int e = 0; e < 8; e++) {
            if (e < m) {
                float4 r;
                r.x = acc[e].x + b4.x;
                r.y = acc[e].y + b4.y;
                r.z = acc[e].z + b4.z;
                r.w = acc[e].w + b4.w;
                *(float4*)(out + (size_t)(base + e) * (3 * HID) + g * HID + 4 * lane) = r;
            }
        }
        __syncwarp();
    }
}

// ---------------- GRU pointwise finish ----------------
__global__ void gru_final_kernel(const float* __restrict__ ns, float* __restrict__ out) {
    int idx = blockIdx.x * blockDim.x + threadIdx.x;
    if (idx >= N_NODES * HID) return;
    int n = idx >> 7;
    int j = idx & 127;
    size_t b = (size_t)n * (3 * HID) + j;
    float ir = g_gi[b], iz = g_gi[b + 128], inn = g_gi[b + 256];
    float hr = g_gh[b], hz = g_gh[b + 128], hn = g_gh[b + 256];
    float r = 1.0f / (1.0f + __expf(-(ir + hr)));
    float z = 1.0f / (1.0f + __expf(-(iz + hz)));
    float nn = tanhf(inn + r * hn);
    out[idx] = (1.0f - z) * nn + z * ns[idx];
}

// ---------------- launch ----------------
extern "C" void kernel_launch(void* const* d_in, const int* in_sizes, int n_in,
                              void* d_out, int out_size) {
    const float* ns    = (const float*)d_in[0];
    const void*  eidx  = d_in[1];
    const void*  etype = d_in[2];
    const float* eW    = (const float*)d_in[3];
    const float* eb    = (const float*)d_in[4];
    const float* wih   = (const float*)d_in[5];
    const float* whh   = (const float*)d_in[6];
    const float* bih   = (const float*)d_in[7];
    const float* bhh   = (const float*)d_in[8];
    float* out = (float*)d_out;

    const int SMEM = (HID * HID + 8 * 8 * HID) * (int)sizeof(float); // 96 KB
    cudaFuncSetAttribute(edge_gemm_kernel, cudaFuncAttributeMaxDynamicSharedMemorySize, SMEM);
    cudaFuncSetAttribute(gru_gemm_kernel,  cudaFuncAttributeMaxDynamicSharedMemorySize, SMEM);

    detect_kernel<<<1, 1>>>((const int*)eidx);
    prep_kernel<<<(N_NODES * HID + 255) / 256, 256>>>(eW, wih, whh);
    bucket_kernel<<<(N_EDGES + 255) / 256, 256>>>(etype);
    edge_gemm_kernel<<<dim3(296, NT), 256, SMEM>>>(ns, eidx, eb);
    gru_gemm_kernel<<<dim3(296, 6), 256, SMEM>>>(ns, bih, bhh);
    gru_final_kernel<<<(N_NODES * HID + 255) / 256, 256>>>(ns, out);
}

// round 3
// speedup vs baseline: 1.1574x; 1.1574x over previous
#include <cuda_runtime.h>

#define N_NODES 50000
#define N_EDGES 625000
#define HID 128
#define NT 4

// ---------------- scratch (device globals; no allocation allowed) ----------------
__device__ float g_agg[N_NODES * HID];
__device__ float g_Wt[NT * HID * HID];           // Wt[t][k][j] = W[t][j][k]
__device__ float g_WihT[3 * HID * HID];
__device__ float g_WhhT[3 * HID * HID];
__device__ float g_gi[(size_t)N_NODES * 3 * HID];
__device__ float g_gh[(size_t)N_NODES * 3 * HID];
__device__ int   g_bucket[NT * N_EDGES];
__device__ int   g_cnt[NT];
__device__ int   g_is64;

__device__ __forceinline__ int load_idx(const void* p, int i, int is64) {
    if (is64) return (int)((const long long*)p)[i];
    return ((const int*)p)[i];
}

__device__ __forceinline__ void red_add_v4(float* ptr, float4 v) {
    asm volatile("red.global.add.v4.f32 [%0], {%1,%2,%3,%4};"
                 :: "l"(ptr), "f"(v.x), "f"(v.y), "f"(v.z), "f"(v.w) : "memory");
}

// ---------------- dtype detect ----------------
__global__ void detect_kernel(const int* __restrict__ ei_as_i32) {
    int ok = 1;
    for (int i = 0; i < 64; i++)
        if (ei_as_i32[2 * i + 1] != 0) ok = 0;
    g_is64 = ok;
}

// ---------------- prep ----------------
__global__ void prep_kernel(const float* __restrict__ eW,
                            const float* __restrict__ wih,
                            const float* __restrict__ whh) {
    int i = blockIdx.x * blockDim.x + threadIdx.x;
    if (i < N_NODES * HID) g_agg[i] = 0.0f;
    if (i < NT * HID * HID) {
        int t = i >> 14, r = i & 16383, k = r >> 7, j = r & 127;
        g_Wt[i] = eW[(t << 14) + (j << 7) + k];
    }
    if (i < 3 * HID * HID) {
        int g = i >> 14, r = i & 16383, k = r >> 7, j = r & 127;
        g_WihT[i] = wih[((g << 7) + j) * HID + k];
        g_WhhT[i] = whh[((g << 7) + j) * HID + k];
    }
    if (i < NT) g_cnt[i] = 0;
}

// ---------------- bucket edges by type ----------------
__global__ void bucket_kernel(const void* __restrict__ etype) {
    int e = blockIdx.x * blockDim.x + threadIdx.x;
    if (e < N_EDGES) {
        int is64 = g_is64;
        int t = load_idx(etype, e, is64) & (NT - 1);
        int pos = atomicAdd(&g_cnt[t], 1);
        g_bucket[t * N_EDGES + pos] = e;
    }
}

// ---------------- edge message GEMM + scatter-add ----------------
// blockIdx.y = type. 8 warps/block; warp tile = 8 edges. W^T[128][128] in SMEM.
// Inner loop: k stepped by 4; x rows read as float4 broadcasts.
__global__ void edge_gemm_kernel(const float* __restrict__ ns,
                                 const void* __restrict__ eidx,
                                 const float* __restrict__ eb) {
    extern __shared__ float smem[];
    float* sW = smem;                // [128][128]
    float* sx = smem + HID * HID;    // [8 warps][8 edges][128]

    int t = blockIdx.y;
    int cnt = g_cnt[t];
    int is64 = g_is64;
    for (int i = threadIdx.x; i < HID * HID; i += blockDim.x)
        sW[i] = g_Wt[t * HID * HID + i];

    int lane = threadIdx.x & 31;
    int warp = threadIdx.x >> 5;
    float4 b4 = *(const float4*)(eb + t * HID + 4 * lane);
    __syncthreads();

    float* sxw = sx + warp * 8 * HID;
    int tiles = (cnt + 7) >> 3;
    int w  = blockIdx.x * (blockDim.x >> 5) + warp;
    int ws = gridDim.x * (blockDim.x >> 5);

    for (int tile = w; tile < tiles; tile += ws) {
        int base = tile * 8;
        int m = min(8, cnt - base);
        int src = 0, dst = 0;
        if (lane < m) {
            int e = g_bucket[t * N_EDGES + base + lane];
            src = load_idx(eidx, e, is64);
            dst = load_idx(eidx, N_EDGES + e, is64);
        }
        #pragma unroll
        for (int e = 0; e < 8; e++) {
            int s = __shfl_sync(0xffffffffu, src, e);
            float4 v = make_float4(0.f, 0.f, 0.f, 0.f);
            if (e < m) v = *(const float4*)(ns + (size_t)s * HID + 4 * lane);
            *(float4*)(sxw + e * HID + 4 * lane) = v;
        }
        __syncwarp();

        float4 acc[8] = {};
        #pragma unroll 4
        for (int k0 = 0; k0 < HID; k0 += 4) {
            float4 xv[8];
            #pragma unroll
            for (int e = 0; e < 8; e++)
                xv[e] = *(const float4*)(sxw + e * HID + k0);
            #pragma unroll
            for (int kk = 0; kk < 4; kk++) {
                float4 w4 = *(const float4*)(sW + (k0 + kk) * HID + 4 * lane);
                #pragma unroll
                for (int e = 0; e < 8; e++) {
                    float xk = (kk == 0) ? xv[e].x : (kk == 1) ? xv[e].y
                             : (kk == 2) ? xv[e].z : xv[e].w;
                    acc[e].x = fmaf(xk, w4.x, acc[e].x);
                    acc[e].y = fmaf(xk, w4.y, acc[e].y);
                    acc[e].z = fmaf(xk, w4.z, acc[e].z);
                    acc[e].w = fmaf(xk, w4.w, acc[e].w);
                }
            }
        }

        #pragma unroll
        for (int e = 0; e < 8; e++) {
            if (e < m) {
                int d = __shfl_sync(0xffffffffu, dst, e);
                float4 r = make_float4(acc[e].x + b4.x, acc[e].y + b4.y,
                                       acc[e].z + b4.z, acc[e].w + b4.w);
                red_add_v4(g_agg + (size_t)d * HID + 4 * lane, r);
            }
        }
        __syncwarp();
    }
}

// ---------------- GRU gate GEMMs ----------------
__global__ void gru_gemm_kernel(const float* __restrict__ ns,
                                const float* __restrict__ bih,
                                const float* __restrict__ bhh) {
    extern __shared__ float smem[];
    float* sW = smem;
    float* sx = smem + HID * HID;

    int s = blockIdx.y;
    int g = (s < 3) ? s : (s - 3);
    bool ih = (s < 3);
    const float* in   = ih ? g_agg : ns;
    const float* wt   = (ih ? g_WihT : g_WhhT) + g * HID * HID;
    const float* bias = (ih ? bih : bhh) + g * HID;
    float* out        = ih ? g_gi : g_gh;

    for (int i = threadIdx.x; i < HID * HID; i += blockDim.x) sW[i] = wt[i];

    int lane = threadIdx.x & 31;
    int warp = threadIdx.x >> 5;
    float4 b4 = *(const float4*)(bias + 4 * lane);
    __syncthreads();

    float* sxw = sx + warp * 8 * HID;
    int tiles = (N_NODES + 7) >> 3;
    int w  = blockIdx.x * (blockDim.x >> 5) + warp;
    int ws = gridDim.x * (blockDim.x >> 5);

    for (int tile = w; tile < tiles; tile += ws) {
        int base = tile * 8;
        int m = min(8, N_NODES - base);
        #pragma unroll
        for (int e = 0; e < 8; e++) {
            float4 v = make_float4(0.f, 0.f, 0.f, 0.f);
            if (e < m) v = *(const float4*)(in + (size_t)(base + e) * HID + 4 * lane);
            *(float4*)(sxw + e * HID + 4 * lane) = v;
        }
        __syncwarp();

        float4 acc[8] = {};
        #pragma unroll 4
        for (int k0 = 0; k0 < HID; k0 += 4) {
            float4 xv[8];
            #pragma unroll
            for (int e = 0; e < 8; e++)
                xv[e] = *(const float4*)(sxw + e * HID + k0);
            #pragma unroll
            for (int kk = 0; kk < 4; kk++) {
                float4 w4 = *(const float4*)(sW + (k0 + kk) * HID + 4 * lane);
                #pragma unroll
                for (int e = 0; e < 8; e++) {
                    float xk = (kk == 0) ? xv[e].x : (kk == 1) ? xv[e].y
                             : (kk == 2) ? xv[e].z : xv[e].w;
                    acc[e].x = fmaf(xk, w4.x, acc[e].x);
                    acc[e].y = fmaf(xk, w4.y, acc[e].y);
                    acc[e].z = fmaf(xk, w4.z, acc[e].z);
                    acc[e].w = fmaf(xk, w4.w, acc[e].w);
                }
            }
        }

        #pragma unroll
        for (int e = 0; e < 8; e++) {
            if (e < m) {
                float4 r = make_float4(acc[e].x + b4.x, acc[e].y + b4.y,
                                       acc[e].z + b4.z, acc[e].w + b4.w);
                *(float4*)(out + (size_t)(base + e) * (3 * HID) + g * HID + 4 * lane) = r;
            }
        }
        __syncwarp();
    }
}

// ---------------- GRU pointwise finish ----------------
__global__ void gru_final_kernel(const float* __restrict__ ns, float* __restrict__ out) {
    int idx = blockIdx.x * blockDim.x + threadIdx.x;
    if (idx >= N_NODES * HID) return;
    int n = idx >> 7;
    int j = idx & 127;
    size_t b = (size_t)n * (3 * HID) + j;
    float ir = g_gi[b], iz = g_gi[b + 128], inn = g_gi[b + 256];
    float hr = g_gh[b], hz = g_gh[b + 128], hn = g_gh[b + 256];
    float r = 1.0f / (1.0f + __expf(-(ir + hr)));
    float z = 1.0f / (1.0f + __expf(-(iz + hz)));
    float nn = tanhf(inn + r * hn);
    out[idx] = (1.0f - z) * nn + z * ns[idx];
}

// ---------------- launch ----------------
extern "C" void kernel_launch(void* const* d_in, const int* in_sizes, int n_in,
                              void* d_out, int out_size) {
    const float* ns    = (const float*)d_in[0];
    const void*  eidx  = d_in[1];
    const void*  etype = d_in[2];
    const float* eW    = (const float*)d_in[3];
    const float* eb    = (const float*)d_in[4];
    const float* wih   = (const float*)d_in[5];
    const float* whh   = (const float*)d_in[6];
    const float* bih   = (const float*)d_in[7];
    const float* bhh   = (const float*)d_in[8];
    float* out = (float*)d_out;

    const int SMEM = (HID * HID + 8 * 8 * HID) * (int)sizeof(float); // 96 KB
    cudaFuncSetAttribute(edge_gemm_kernel, cudaFuncAttributeMaxDynamicSharedMemorySize, SMEM);
    cudaFuncSetAttribute(gru_gemm_kernel,  cudaFuncAttributeMaxDynamicSharedMemorySize, SMEM);

    detect_kernel<<<1, 1>>>((const int*)eidx);
    prep_kernel<<<(N_NODES * HID + 255) / 256, 256>>>(eW, wih, whh);
    bucket_kernel<<<(N_EDGES + 255) / 256, 256>>>(etype);
    edge_gemm_kernel<<<dim3(296, NT), 256, SMEM>>>(ns, eidx, eb);
    gru_gemm_kernel<<<dim3(296, 6), 256, SMEM>>>(ns, bih, bhh);
    gru_final_kernel<<<(N_NODES * HID + 255) / 256, 256>>>(ns, out);
}

// round 4
// speedup vs baseline: 1.7481x; 1.5104x over previous
#include <cuda_runtime.h>

#define N_NODES 50000
#define N_EDGES 625000
#define HID 128
#define NT 4

// ---------------- scratch (device globals; no allocation allowed) ----------------
__device__ float g_agg[N_NODES * HID];                       // 25.6 MB
__device__ float g_aggT[(size_t)NT * N_NODES * HID];         // 102.4 MB per-type x sums
__device__ float g_Wt[NT * HID * HID];                       // Wt[t][k][j] = W[t][j][k]
__device__ float g_WihT[3 * HID * HID];
__device__ float g_WhhT[3 * HID * HID];
__device__ float g_gi[(size_t)N_NODES * 3 * HID];
__device__ float g_gh[(size_t)N_NODES * 3 * HID];
__device__ int   g_deg[N_NODES];
__device__ int   g_off[N_NODES + 1];
__device__ int   g_fill[N_NODES];
__device__ int   g_elist[N_EDGES];                           // edge ids grouped by dst
__device__ int   g_is64;

__device__ __forceinline__ int load_idx(const void* p, int i, int is64) {
    if (is64) return (int)((const long long*)p)[i];
    return ((const int*)p)[i];
}

__device__ __forceinline__ void red_add_v4(float* ptr, float4 v) {
    asm volatile("red.global.add.v4.f32 [%0], {%1,%2,%3,%4};"
                 :: "l"(ptr), "f"(v.x), "f"(v.y), "f"(v.z), "f"(v.w) : "memory");
}

// ---------------- dtype detect ----------------
__global__ void detect_kernel(const int* __restrict__ ei_as_i32) {
    int ok = 1;
    for (int i = 0; i < 64; i++)
        if (ei_as_i32[2 * i + 1] != 0) ok = 0;
    g_is64 = ok;
}

// ---------------- prep: zero deg, transpose weights ----------------
__global__ void prep_kernel(const float* __restrict__ eW,
                            const float* __restrict__ wih,
                            const float* __restrict__ whh) {
    int i = blockIdx.x * blockDim.x + threadIdx.x;
    if (i < NT * HID * HID) {
        int t = i >> 14, r = i & 16383, k = r >> 7, j = r & 127;
        g_Wt[i] = eW[(t << 14) + (j << 7) + k];
    }
    if (i < 3 * HID * HID) {
        int g = i >> 14, r = i & 16383, k = r >> 7, j = r & 127;
        g_WihT[i] = wih[((g << 7) + j) * HID + k];
        g_WhhT[i] = whh[((g << 7) + j) * HID + k];
    }
    if (i < N_NODES) g_deg[i] = 0;
}

// ---------------- CSR by destination ----------------
__global__ void hist_kernel(const void* __restrict__ eidx) {
    int e = blockIdx.x * blockDim.x + threadIdx.x;
    if (e < N_EDGES) {
        int d = load_idx(eidx, N_EDGES + e, g_is64);
        atomicAdd(&g_deg[d], 1);
    }
}

// single-block scan: 1024 threads, 49 nodes/thread
__global__ void scan_kernel() {
    __shared__ int part[1024];
    const int NPT = (N_NODES + 1023) / 1024;  // 49
    int tid = threadIdx.x;
    int start = tid * NPT, end = min(start + NPT, N_NODES);
    int s = 0;
    for (int i = start; i < end; i++) s += g_deg[i];
    part[tid] = s;
    __syncthreads();
    for (int d = 1; d < 1024; d <<= 1) {
        int v = (tid >= d) ? part[tid - d] : 0;
        __syncthreads();
        part[tid] += v;
        __syncthreads();
    }
    int excl = (tid == 0) ? 0 : part[tid - 1];
    for (int i = start; i < end; i++) {
        g_off[i] = excl;
        g_fill[i] = excl;
        excl += g_deg[i];
    }
    if (tid == 1023) g_off[N_NODES] = part[1023];
}

__global__ void fill_kernel(const void* __restrict__ eidx) {
    int e = blockIdx.x * blockDim.x + threadIdx.x;
    if (e < N_EDGES) {
        int d = load_idx(eidx, N_EDGES + e, g_is64);
        int pos = atomicAdd(&g_fill[d], 1);
        g_elist[pos] = e;
    }
}

// ---------------- per-node accumulation (warp per node, no atomics) ----------------
// acc[t] += x_src for each in-edge of type t; writes aggT rows + count-bias row of g_agg.
__global__ void accum_kernel(const float* __restrict__ ns,
                             const void* __restrict__ eidx,
                             const void* __restrict__ etype,
                             const float* __restrict__ eb) {
    int w = (blockIdx.x * blockDim.x + threadIdx.x) >> 5;
    int lane = threadIdx.x & 31;
    if (w >= N_NODES) return;
    int is64 = g_is64;
    int s0 = g_off[w], s1 = g_off[w + 1];

    float4 a0 = {0,0,0,0}, a1 = a0, a2 = a0, a3 = a0;
    int c0 = 0, c1 = 0, c2 = 0, c3 = 0;

    for (int base = s0; base < s1; base += 32) {
        int nn = min(32, s1 - base);
        int src = 0, t = 0;
        if (lane < nn) {
            int eid = g_elist[base + lane];
            src = load_idx(eidx, eid, is64);
            t = load_idx(etype, eid, is64) & (NT - 1);
        }
        for (int j = 0; j < nn; j++) {
            int s  = __shfl_sync(0xffffffffu, src, j);
            int tt = __shfl_sync(0xffffffffu, t, j);
            float4 v = *(const float4*)(ns + (size_t)s * HID + 4 * lane);
            if (tt == 0)      { a0.x += v.x; a0.y += v.y; a0.z += v.z; a0.w += v.w; c0++; }
            else if (tt == 1) { a1.x += v.x; a1.y += v.y; a1.z += v.z; a1.w += v.w; c1++; }
            else if (tt == 2) { a2.x += v.x; a2.y += v.y; a2.z += v.z; a2.w += v.w; c2++; }
            else              { a3.x += v.x; a3.y += v.y; a3.z += v.z; a3.w += v.w; c3++; }
        }
    }

    size_t row = (size_t)w * HID + 4 * lane;
    *(float4*)(g_aggT + 0 * (size_t)N_NODES * HID + row) = a0;
    *(float4*)(g_aggT + 1 * (size_t)N_NODES * HID + row) = a1;
    *(float4*)(g_aggT + 2 * (size_t)N_NODES * HID + row) = a2;
    *(float4*)(g_aggT + 3 * (size_t)N_NODES * HID + row) = a3;

    float4 b0 = *(const float4*)(eb + 0 * HID + 4 * lane);
    float4 b1 = *(const float4*)(eb + 1 * HID + 4 * lane);
    float4 b2 = *(const float4*)(eb + 2 * HID + 4 * lane);
    float4 b3 = *(const float4*)(eb + 3 * HID + 4 * lane);
    float4 r;
    r.x = c0 * b0.x + c1 * b1.x + c2 * b2.x + c3 * b3.x;
    r.y = c0 * b0.y + c1 * b1.y + c2 * b2.y + c3 * b3.y;
    r.z = c0 * b0.z + c1 * b1.z + c2 * b2.z + c3 * b3.z;
    r.w = c0 * b0.w + c1 * b1.w + c2 * b2.w + c3 * b3.w;
    *(float4*)(g_agg + row) = r;
}

// ---------------- per-type dense GEMM: g_agg += aggT[t] @ W[t].T ----------------
// blockIdx.y = t. 8 warps, warp tile = 8 nodes, W^T in SMEM. red.add epilogue.
__global__ void agg_gemm_kernel() {
    extern __shared__ float smem[];
    float* sW = smem;                // [128][128]
    float* sx = smem + HID * HID;    // [8 warps][8 rows][128]

    int t = blockIdx.y;
    const float* in = g_aggT + (size_t)t * N_NODES * HID;
    for (int i = threadIdx.x; i < HID * HID; i += blockDim.x)
        sW[i] = g_Wt[t * HID * HID + i];

    int lane = threadIdx.x & 31;
    int warp = threadIdx.x >> 5;
    __syncthreads();

    float* sxw = sx + warp * 8 * HID;
    int tiles = (N_NODES + 7) >> 3;
    int w  = blockIdx.x * (blockDim.x >> 5) + warp;
    int ws = gridDim.x * (blockDim.x >> 5);

    for (int tile = w; tile < tiles; tile += ws) {
        int base = tile * 8;
        int m = min(8, N_NODES - base);
        #pragma unroll
        for (int e = 0; e < 8; e++) {
            float4 v = make_float4(0.f, 0.f, 0.f, 0.f);
            if (e < m) v = *(const float4*)(in + (size_t)(base + e) * HID + 4 * lane);
            *(float4*)(sxw + e * HID + 4 * lane) = v;
        }
        __syncwarp();

        float4 acc[8] = {};
        #pragma unroll 4
        for (int k0 = 0; k0 < HID; k0 += 4) {
            float4 xv[8];
            #pragma unroll
            for (int e = 0; e < 8; e++)
                xv[e] = *(const float4*)(sxw + e * HID + k0);
            #pragma unroll
            for (int kk = 0; kk < 4; kk++) {
                float4 w4 = *(const float4*)(sW + (k0 + kk) * HID + 4 * lane);
                #pragma unroll
                for (int e = 0; e < 8; e++) {
                    float xk = (kk == 0) ? xv[e].x : (kk == 1) ? xv[e].y
                             : (kk == 2) ? xv[e].z : xv[e].w;
                    acc[e].x = fmaf(xk, w4.x, acc[e].x);
                    acc[e].y = fmaf(xk, w4.y, acc[e].y);
                    acc[e].z = fmaf(xk, w4.z, acc[e].z);
                    acc[e].w = fmaf(xk, w4.w, acc[e].w);
                }
            }
        }

        #pragma unroll
        for (int e = 0; e < 8; e++)
            if (e < m)
                red_add_v4(g_agg + (size_t)(base + e) * HID + 4 * lane, acc[e]);
        __syncwarp();
    }
}

// ---------------- GRU gate GEMMs ----------------
__global__ void gru_gemm_kernel(const float* __restrict__ ns,
                                const float* __restrict__ bih,
                                const float* __restrict__ bhh) {
    extern __shared__ float smem[];
    float* sW = smem;
    float* sx = smem + HID * HID;

    int s = blockIdx.y;
    int g = (s < 3) ? s : (s - 3);
    bool ih = (s < 3);
    const float* in   = ih ? g_agg : ns;
    const float* wt   = (ih ? g_WihT : g_WhhT) + g * HID * HID;
    const float* bias = (ih ? bih : bhh) + g * HID;
    float* out        = ih ? g_gi : g_gh;

    for (int i = threadIdx.x; i < HID * HID; i += blockDim.x) sW[i] = wt[i];

    int lane = threadIdx.x & 31;
    int warp = threadIdx.x >> 5;
    float4 b4 = *(const float4*)(bias + 4 * lane);
    __syncthreads();

    float* sxw = sx + warp * 8 * HID;
    int tiles = (N_NODES + 7) >> 3;
    int w  = blockIdx.x * (blockDim.x >> 5) + warp;
    int ws = gridDim.x * (blockDim.x >> 5);

    for (int tile = w; tile < tiles; tile += ws) {
        int base = tile * 8;
        int m = min(8, N_NODES - base);
        #pragma unroll
        for (int e = 0; e < 8; e++) {
            float4 v = make_float4(0.f, 0.f, 0.f, 0.f);
            if (e < m) v = *(const float4*)(in + (size_t)(base + e) * HID + 4 * lane);
            *(float4*)(sxw + e * HID + 4 * lane) = v;
        }
        __syncwarp();

        float4 acc[8] = {};
        #pragma unroll 4
        for (int k0 = 0; k0 < HID; k0 += 4) {
            float4 xv[8];
            #pragma unroll
            for (int e = 0; e < 8; e++)
                xv[e] = *(const float4*)(sxw + e * HID + k0);
            #pragma unroll
            for (int kk = 0; kk < 4; kk++) {
                float4 w4 = *(const float4*)(sW + (k0 + kk) * HID + 4 * lane);
                #pragma unroll
                for (int e = 0; e < 8; e++) {
                    float xk = (kk == 0) ? xv[e].x : (kk == 1) ? xv[e].y
                             : (kk == 2) ? xv[e].z : xv[e].w;
                    acc[e].x = fmaf(xk, w4.x, acc[e].x);
                    acc[e].y = fmaf(xk, w4.y, acc[e].y);
                    acc[e].z = fmaf(xk, w4.z, acc[e].z);
                    acc[e].w = fmaf(xk, w4.w, acc[e].w);
                }
            }
        }

        #pragma unroll
        for (int e = 0; e < 8; e++) {
            if (e < m) {
                float4 r = make_float4(acc[e].x + b4.x, acc[e].y + b4.y,
                                       acc[e].z + b4.z, acc[e].w + b4.w);
                *(float4*)(out + (size_t)(base + e) * (3 * HID) + g * HID + 4 * lane) = r;
            }
        }
        __syncwarp();
    }
}

// ---------------- GRU pointwise finish ----------------
__global__ void gru_final_kernel(const float* __restrict__ ns, float* __restrict__ out) {
    int idx = blockIdx.x * blockDim.x + threadIdx.x;
    if (idx >= N_NODES * HID) return;
    int n = idx >> 7;
    int j = idx & 127;
    size_t b = (size_t)n * (3 * HID) + j;
    float ir = g_gi[b], iz = g_gi[b + 128], inn = g_gi[b + 256];
    float hr = g_gh[b], hz = g_gh[b + 128], hn = g_gh[b + 256];
    float r = 1.0f / (1.0f + __expf(-(ir + hr)));
    float z = 1.0f / (1.0f + __expf(-(iz + hz)));
    float nn = tanhf(inn + r * hn);
    out[idx] = (1.0f - z) * nn + z * ns[idx];
}

// ---------------- launch ----------------
extern "C" void kernel_launch(void* const* d_in, const int* in_sizes, int n_in,
                              void* d_out, int out_size) {
    const float* ns    = (const float*)d_in[0];
    const void*  eidx  = d_in[1];
    const void*  etype = d_in[2];
    const float* eW    = (const float*)d_in[3];
    const float* eb    = (const float*)d_in[4];
    const float* wih   = (const float*)d_in[5];
    const float* whh   = (const float*)d_in[6];
    const float* bih   = (const float*)d_in[7];
    const float* bhh   = (const float*)d_in[8];
    float* out = (float*)d_out;

    const int SMEM = (HID * HID + 8 * 8 * HID) * (int)sizeof(float); // 96 KB
    cudaFuncSetAttribute(agg_gemm_kernel, cudaFuncAttributeMaxDynamicSharedMemorySize, SMEM);
    cudaFuncSetAttribute(gru_gemm_kernel, cudaFuncAttributeMaxDynamicSharedMemorySize, SMEM);

    detect_kernel<<<1, 1>>>((const int*)eidx);
    prep_kernel<<<(NT * HID * HID + 255) / 256, 256>>>(eW, wih, whh);
    hist_kernel<<<(N_EDGES + 255) / 256, 256>>>(eidx);
    scan_kernel<<<1, 1024>>>();
    fill_kernel<<<(N_EDGES + 255) / 256, 256>>>(eidx);
    accum_kernel<<<(N_NODES * 32 + 255) / 256, 256>>>(ns, eidx, etype, eb);
    agg_gemm_kernel<<<dim3(296, NT), 256, SMEM>>>();
    gru_gemm_kernel<<<dim3(296, 6), 256, SMEM>>>(ns, bih, bhh);
    gru_final_kernel<<<(N_NODES * HID + 255) / 256, 256>>>(ns, out);
}

// round 5
// speedup vs baseline: 2.0072x; 1.1482x over previous
#include <cuda_runtime.h>
#include <mma.h>
using namespace nvcuda;

#define N_NODES 50000
#define N_EDGES 625000
#define HID 128
#define NT 4
#define LDA 136   // 128 + 8 pad (floats)

// ---------------- scratch (device globals) ----------------
__device__ float g_agg[N_NODES * HID];
__device__ float g_aggT[(size_t)NT * N_NODES * HID];
__device__ float g_Wt[NT * HID * HID];      // Wt[t][k][j] = W[t][j][k]
__device__ float g_WihT[3 * HID * HID];
__device__ float g_WhhT[3 * HID * HID];
__device__ float g_gi[(size_t)N_NODES * 3 * HID];
__device__ float g_gh[(size_t)N_NODES * 3 * HID];
__device__ int   g_deg[N_NODES];
__device__ int   g_off[N_NODES + 1];
__device__ int   g_fill[N_NODES];
__device__ int   g_elist[N_EDGES];
__device__ int   g_bsum[256];
__device__ int   g_bbase[256];
__device__ int   g_total;
__device__ int   g_is64;

__device__ __forceinline__ int load_idx(const void* p, int i, int is64) {
    if (is64) return (int)((const long long*)p)[i];
    return ((const int*)p)[i];
}

__device__ __forceinline__ void red_add_v4(float* ptr, float4 v) {
    asm volatile("red.global.add.v4.f32 [%0], {%1,%2,%3,%4};"
                 :: "l"(ptr), "f"(v.x), "f"(v.y), "f"(v.z), "f"(v.w) : "memory");
}

// ---------------- dtype detect ----------------
__global__ void detect_kernel(const int* __restrict__ ei_as_i32) {
    int ok = 1;
    for (int i = 0; i < 64; i++)
        if (ei_as_i32[2 * i + 1] != 0) ok = 0;
    g_is64 = ok;
}

// ---------------- prep ----------------
__global__ void prep_kernel(const float* __restrict__ eW,
                            const float* __restrict__ wih,
                            const float* __restrict__ whh) {
    int i = blockIdx.x * blockDim.x + threadIdx.x;
    if (i < NT * HID * HID) {
        int t = i >> 14, r = i & 16383, k = r >> 7, j = r & 127;
        g_Wt[i] = eW[(t << 14) + (j << 7) + k];
    }
    if (i < 3 * HID * HID) {
        int g = i >> 14, r = i & 16383, k = r >> 7, j = r & 127;
        g_WihT[i] = wih[((g << 7) + j) * HID + k];
        g_WhhT[i] = whh[((g << 7) + j) * HID + k];
    }
    if (i < N_NODES) g_deg[i] = 0;
}

// ---------------- CSR by destination ----------------
__global__ void hist_kernel(const void* __restrict__ eidx) {
    int e = blockIdx.x * blockDim.x + threadIdx.x;
    if (e < N_EDGES) {
        int d = load_idx(eidx, N_EDGES + e, g_is64);
        atomicAdd(&g_deg[d], 1);
    }
}

// 3-phase scan: p1 block-reduce, p2 scan of block sums, p3 local scan + base
__global__ void scan_p1() {
    __shared__ int sh[256];
    int i = blockIdx.x * 256 + threadIdx.x;
    sh[threadIdx.x] = (i < N_NODES) ? g_deg[i] : 0;
    __syncthreads();
    for (int d = 128; d > 0; d >>= 1) {
        if (threadIdx.x < d) sh[threadIdx.x] += sh[threadIdx.x + d];
        __syncthreads();
    }
    if (threadIdx.x == 0) g_bsum[blockIdx.x] = sh[0];
}

__global__ void scan_p2(int nblocks) {
    __shared__ int sh[256];
    int t = threadIdx.x;
    int v = (t < nblocks) ? g_bsum[t] : 0;
    sh[t] = v;
    __syncthreads();
    for (int d = 1; d < 256; d <<= 1) {
        int x = (t >= d) ? sh[t - d] : 0;
        __syncthreads();
        sh[t] += x;
        __syncthreads();
    }
    g_bbase[t] = sh[t] - v;  // exclusive
    if (t == 255) g_total = sh[255];
}

__global__ void scan_p3() {
    __shared__ int sh[256];
    int t = threadIdx.x;
    int i = blockIdx.x * 256 + t;
    int v = (i < N_NODES) ? g_deg[i] : 0;
    sh[t] = v;
    __syncthreads();
    for (int d = 1; d < 256; d <<= 1) {
        int x = (t >= d) ? sh[t - d] : 0;
        __syncthreads();
        sh[t] += x;
        __syncthreads();
    }
    if (i < N_NODES) {
        int o = g_bbase[blockIdx.x] + sh[t] - v;
        g_off[i] = o;
        g_fill[i] = o;
    }
    if (blockIdx.x == 0 && t == 0) g_off[N_NODES] = g_total;
}

__global__ void fill_kernel(const void* __restrict__ eidx) {
    int e = blockIdx.x * blockDim.x + threadIdx.x;
    if (e < N_EDGES) {
        int d = load_idx(eidx, N_EDGES + e, g_is64);
        int pos = atomicAdd(&g_fill[d], 1);
        g_elist[pos] = e;
    }
}

// ---------------- per-node accumulation (warp per node) ----------------
__global__ void accum_kernel(const float* __restrict__ ns,
                             const void* __restrict__ eidx,
                             const void* __restrict__ etype,
                             const float* __restrict__ eb) {
    int w = (blockIdx.x * blockDim.x + threadIdx.x) >> 5;
    int lane = threadIdx.x & 31;
    if (w >= N_NODES) return;
    int is64 = g_is64;
    int s0 = g_off[w], s1 = g_off[w + 1];

    float4 a0 = {0,0,0,0}, a1 = a0, a2 = a0, a3 = a0;
    int c0 = 0, c1 = 0, c2 = 0, c3 = 0;

    for (int base = s0; base < s1; base += 32) {
        int nn = min(32, s1 - base);
        int src = 0, t = 0;
        if (lane < nn) {
            int eid = g_elist[base + lane];
            src = load_idx(eidx, eid, is64);
            t = load_idx(etype, eid, is64) & (NT - 1);
        }
        for (int j = 0; j < nn; j++) {
            int s  = __shfl_sync(0xffffffffu, src, j);
            int tt = __shfl_sync(0xffffffffu, t, j);
            float4 v = *(const float4*)(ns + (size_t)s * HID + 4 * lane);
            if (tt == 0)      { a0.x += v.x; a0.y += v.y; a0.z += v.z; a0.w += v.w; c0++; }
            else if (tt == 1) { a1.x += v.x; a1.y += v.y; a1.z += v.z; a1.w += v.w; c1++; }
            else if (tt == 2) { a2.x += v.x; a2.y += v.y; a2.z += v.z; a2.w += v.w; c2++; }
            else              { a3.x += v.x; a3.y += v.y; a3.z += v.z; a3.w += v.w; c3++; }
        }
    }

    size_t row = (size_t)w * HID + 4 * lane;
    *(float4*)(g_aggT + 0 * (size_t)N_NODES * HID + row) = a0;
    *(float4*)(g_aggT + 1 * (size_t)N_NODES * HID + row) = a1;
    *(float4*)(g_aggT + 2 * (size_t)N_NODES * HID + row) = a2;
    *(float4*)(g_aggT + 3 * (size_t)N_NODES * HID + row) = a3;

    float4 b0 = *(const float4*)(eb + 0 * HID + 4 * lane);
    float4 b1 = *(const float4*)(eb + 1 * HID + 4 * lane);
    float4 b2 = *(const float4*)(eb + 2 * HID + 4 * lane);
    float4 b3 = *(const float4*)(eb + 3 * HID + 4 * lane);
    float4 r;
    r.x = c0 * b0.x + c1 * b1.x + c2 * b2.x + c3 * b3.x;
    r.y = c0 * b0.y + c1 * b1.y + c2 * b2.y + c3 * b3.y;
    r.z = c0 * b0.z + c1 * b1.z + c2 * b2.z + c3 * b3.z;
    r.w = c0 * b0.w + c1 * b1.w + c2 * b2.w + c3 * b3.w;
    *(float4*)(g_agg + row) = r;
}

// ---------------- WMMA tf32 GEMM over slices ----------------
// slice s: [0,4)   agg type t : in=aggT[t], W=Wt[t],   out: red.add -> g_agg
//          [4,7)   gh gate g  : in=ns,      W=WhhT[g], out: g_gh (+bhh)
//          [7,10)  gi gate g  : in=g_agg,   W=WihT[g], out: g_gi (+bih)
__global__ void wgemm_kernel(const float* __restrict__ ns,
                             const float* __restrict__ bih,
                             const float* __restrict__ bhh,
                             int slice_base) {
    extern __shared__ float smem[];
    float* sA = smem;                 // [128][LDA]
    float* sB = smem + 128 * LDA;     // [128][LDA]  (k-major)

    int s = slice_base + blockIdx.y;
    const float* in; const float* W;
    float* outp = nullptr; const float* bias = nullptr;
    int colbase = 0, mode;
    if (s < NT) {
        in = g_aggT + (size_t)s * N_NODES * HID; W = g_Wt + s * HID * HID; mode = 0;
    } else if (s < NT + 3) {
        int g = s - NT;
        in = ns; W = g_WhhT + g * HID * HID; outp = g_gh; bias = bhh + g * HID;
        colbase = g * HID; mode = 1;
    } else {
        int g = s - NT - 3;
        in = g_agg; W = g_WihT + g * HID * HID; outp = g_gi; bias = bih + g * HID;
        colbase = g * HID; mode = 1;
    }

    int row0 = blockIdx.x * 128;
    int m = min(128, N_NODES - row0);

    // stage B (weights, k-major) and A (input rows) into SMEM
    for (int i = threadIdx.x; i < HID * HID / 4; i += blockDim.x) {
        int k = i >> 5, j4 = i & 31;
        *(float4*)(sB + k * LDA + 4 * j4) = *(const float4*)(W + k * HID + 4 * j4);
    }
    for (int i = threadIdx.x; i < 128 * HID / 4; i += blockDim.x) {
        int r = i >> 5, c4 = i & 31;
        float4 v = make_float4(0.f, 0.f, 0.f, 0.f);
        if (r < m) v = *(const float4*)(in + (size_t)(row0 + r) * HID + 4 * c4);
        *(float4*)(sA + r * LDA + 4 * c4) = v;
    }
    __syncthreads();

    int warp = threadIdx.x >> 5;
    int wr = warp >> 2;   // 0..1 : rows 64*wr..
    int wc = warp & 3;    // 0..3 : cols 32*wc..

    wmma::fragment<wmma::accumulator, 16, 16, 8, float> acc[4][2];
    #pragma unroll
    for (int a = 0; a < 4; a++)
        #pragma unroll
        for (int b = 0; b < 2; b++)
            wmma::fill_fragment(acc[a][b], 0.0f);

    #pragma unroll
    for (int k = 0; k < HID; k += 8) {
        wmma::fragment<wmma::matrix_a, 16, 16, 8, wmma::precision::tf32, wmma::row_major> af[4];
        wmma::fragment<wmma::matrix_b, 16, 16, 8, wmma::precision::tf32, wmma::row_major> bf[2];
        #pragma unroll
        for (int a = 0; a < 4; a++) {
            wmma::load_matrix_sync(af[a], sA + (64 * wr + 16 * a) * LDA + k, LDA);
            #pragma unroll
            for (int i = 0; i < af[a].num_elements; i++)
                af[a].x[i] = wmma::__float_to_tf32(af[a].x[i]);
        }
        #pragma unroll
        for (int b = 0; b < 2; b++) {
            wmma::load_matrix_sync(bf[b], sB + k * LDA + 32 * wc + 16 * b, LDA);
            #pragma unroll
            for (int i = 0; i < bf[b].num_elements; i++)
                bf[b].x[i] = wmma::__float_to_tf32(bf[b].x[i]);
        }
        #pragma unroll
        for (int a = 0; a < 4; a++)
            #pragma unroll
            for (int b = 0; b < 2; b++)
                wmma::mma_sync(acc[a][b], af[a], bf[b], acc[a][b]);
    }
    __syncthreads();

    // write accumulators to sA, then epilogue
    #pragma unroll
    for (int a = 0; a < 4; a++)
        #pragma unroll
        for (int b = 0; b < 2; b++)
            wmma::store_matrix_sync(sA + (64 * wr + 16 * a) * LDA + 32 * wc + 16 * b,
                                    acc[a][b], LDA, wmma::mem_row_major);
    __syncthreads();

    for (int i = threadIdx.x; i < 128 * 32; i += blockDim.x) {
        int r = i >> 5, c4 = i & 31;
        if (r < m) {
            float4 v = *(float4*)(sA + r * LDA + 4 * c4);
            if (mode == 0) {
                red_add_v4(g_agg + (size_t)(row0 + r) * HID + 4 * c4, v);
            } else {
                float4 bb = *(const float4*)(bias + 4 * c4);
                v.x += bb.x; v.y += bb.y; v.z += bb.z; v.w += bb.w;
                *(float4*)(outp + (size_t)(row0 + r) * (3 * HID) + colbase + 4 * c4) = v;
            }
        }
    }
}

// ---------------- GRU pointwise finish ----------------
__global__ void gru_final_kernel(const float* __restrict__ ns, float* __restrict__ out) {
    int idx = blockIdx.x * blockDim.x + threadIdx.x;
    if (idx >= N_NODES * HID) return;
    int n = idx >> 7;
    int j = idx & 127;
    size_t b = (size_t)n * (3 * HID) + j;
    float ir = g_gi[b], iz = g_gi[b + 128], inn = g_gi[b + 256];
    float hr = g_gh[b], hz = g_gh[b + 128], hn = g_gh[b + 256];
    float r = 1.0f / (1.0f + __expf(-(ir + hr)));
    float z = 1.0f / (1.0f + __expf(-(iz + hz)));
    float nn = tanhf(inn + r * hn);
    out[idx] = (1.0f - z) * nn + z * ns[idx];
}

// ---------------- launch ----------------
extern "C" void kernel_launch(void* const* d_in, const int* in_sizes, int n_in,
                              void* d_out, int out_size) {
    const float* ns    = (const float*)d_in[0];
    const void*  eidx  = d_in[1];
    const void*  etype = d_in[2];
    const float* eW    = (const float*)d_in[3];
    const float* eb    = (const float*)d_in[4];
    const float* wih   = (const float*)d_in[5];
    const float* whh   = (const float*)d_in[6];
    const float* bih   = (const float*)d_in[7];
    const float* bhh   = (const float*)d_in[8];
    float* out = (float*)d_out;

    const int GSMEM = 2 * 128 * LDA * (int)sizeof(float); // 139264 B
    cudaFuncSetAttribute(wgemm_kernel, cudaFuncAttributeMaxDynamicSharedMemorySize, GSMEM);

    const int SCAN_BLOCKS = (N_NODES + 255) / 256; // 196
    const int GEMM_BLOCKS = (N_NODES + 127) / 128; // 391

    detect_kernel<<<1, 1>>>((const int*)eidx);
    prep_kernel<<<(NT * HID * HID + 255) / 256, 256>>>(eW, wih, whh);
    hist_kernel<<<(N_EDGES + 255) / 256, 256>>>(eidx);
    scan_p1<<<SCAN_BLOCKS, 256>>>();
    scan_p2<<<1, 256>>>(SCAN_BLOCKS);
    scan_p3<<<SCAN_BLOCKS, 256>>>();
    fill_kernel<<<(N_EDGES + 255) / 256, 256>>>(eidx);
    accum_kernel<<<(N_NODES * 32 + 255) / 256, 256>>>(ns, eidx, etype, eb);
    wgemm_kernel<<<dim3(GEMM_BLOCKS, 7), 256, GSMEM>>>(ns, bih, bhh, 0);  // 4 agg + 3 gh
    wgemm_kernel<<<dim3(GEMM_BLOCKS, 3), 256, GSMEM>>>(ns, bih, bhh, 7);  // 3 gi
    gru_final_kernel<<<(N_NODES * HID + 255) / 256, 256>>>(ns, out);
}

// round 11
// speedup vs baseline: 2.0238x; 1.0083x over previous
#include <cuda_runtime.h>
#include <cstdint>
#include <mma.h>
using namespace nvcuda;

#define N_NODES 50000
#define N_EDGES 625000
#define HID 128
#define NT 4
#define LDA 136   // 128 + 8 pad (floats)

// ---------------- scratch (device globals) ----------------
__device__ float g_agg[N_NODES * HID];
__device__ float g_aggT[(size_t)NT * N_NODES * HID];
__device__ float g_Wt[NT * HID * HID];      // Wt[t][k][j] = W[t][j][k]
__device__ float g_WihT[3 * HID * HID];
__device__ float g_WhhT[3 * HID * HID];
__device__ float g_gi[(size_t)N_NODES * 3 * HID];
__device__ float g_gh[(size_t)N_NODES * 3 * HID];
__device__ int   g_deg[N_NODES];
__device__ int   g_off[N_NODES + 1];
__device__ int   g_fill[N_NODES];
__device__ int   g_elist[N_EDGES];
__device__ int   g_bsum[256];
__device__ int   g_bbase[256];
__device__ int   g_total;
__device__ int   g_is64;

__device__ __forceinline__ int load_idx(const void* p, int i, int is64) {
    if (is64) return (int)((const long long*)p)[i];
    return ((const int*)p)[i];
}

__device__ __forceinline__ void red_add_v4(float* ptr, float4 v) {
    asm volatile("red.global.add.v4.f32 [%0], {%1,%2,%3,%4};"
                 :: "l"(ptr), "f"(v.x), "f"(v.y), "f"(v.z), "f"(v.w) : "memory");
}

__device__ __forceinline__ float f2tf32f(float x) {
    uint32_t o;
    asm("cvt.rna.tf32.f32 %0, %1;" : "=r"(o) : "f"(x));
    return __uint_as_float(o);
}

__device__ __forceinline__ float4 round4(float4 v) {
    return make_float4(f2tf32f(v.x), f2tf32f(v.y), f2tf32f(v.z), f2tf32f(v.w));
}

// ---------------- dtype detect ----------------
__global__ void detect_kernel(const int* __restrict__ ei_as_i32) {
    int ok = 1;
    for (int i = 0; i < 64; i++)
        if (ei_as_i32[2 * i + 1] != 0) ok = 0;
    g_is64 = ok;
}

// ---------------- prep: zero deg, transpose weights (k-major) ----------------
__global__ void prep_kernel(const float* __restrict__ eW,
                            const float* __restrict__ wih,
                            const float* __restrict__ whh) {
    int i = blockIdx.x * blockDim.x + threadIdx.x;
    if (i < NT * HID * HID) {
        int t = i >> 14, r = i & 16383, k = r >> 7, j = r & 127;
        g_Wt[i] = eW[(t << 14) + (j << 7) + k];
    }
    if (i < 3 * HID * HID) {
        int g = i >> 14, r = i & 16383, k = r >> 7, j = r & 127;
        g_WihT[i] = wih[((g << 7) + j) * HID + k];
        g_WhhT[i] = whh[((g << 7) + j) * HID + k];
    }
    if (i < N_NODES) g_deg[i] = 0;
}

// ---------------- CSR by destination ----------------
__global__ void hist_kernel(const void* __restrict__ eidx) {
    int e = blockIdx.x * blockDim.x + threadIdx.x;
    if (e < N_EDGES) {
        int d = load_idx(eidx, N_EDGES + e, g_is64);
        atomicAdd(&g_deg[d], 1);
    }
}

__global__ void scan_p1() {
    __shared__ int sh[256];
    int i = blockIdx.x * 256 + threadIdx.x;
    sh[threadIdx.x] = (i < N_NODES) ? g_deg[i] : 0;
    __syncthreads();
    for (int d = 128; d > 0; d >>= 1) {
        if (threadIdx.x < d) sh[threadIdx.x] += sh[threadIdx.x + d];
        __syncthreads();
    }
    if (threadIdx.x == 0) g_bsum[blockIdx.x] = sh[0];
}

__global__ void scan_p2(int nblocks) {
    __shared__ int sh[256];
    int t = threadIdx.x;
    int v = (t < nblocks) ? g_bsum[t] : 0;
    sh[t] = v;
    __syncthreads();
    for (int d = 1; d < 256; d <<= 1) {
        int x = (t >= d) ? sh[t - d] : 0;
        __syncthreads();
        sh[t] += x;
        __syncthreads();
    }
    g_bbase[t] = sh[t] - v;
    if (t == 255) g_total = sh[255];
}

__global__ void scan_p3() {
    __shared__ int sh[256];
    int t = threadIdx.x;
    int i = blockIdx.x * 256 + t;
    int v = (i < N_NODES) ? g_deg[i] : 0;
    sh[t] = v;
    __syncthreads();
    for (int d = 1; d < 256; d <<= 1) {
        int x = (t >= d) ? sh[t - d] : 0;
        __syncthreads();
        sh[t] += x;
        __syncthreads();
    }
    if (i < N_NODES) {
        int o = g_bbase[blockIdx.x] + sh[t] - v;
        g_off[i] = o;
        g_fill[i] = o;
    }
    if (blockIdx.x == 0 && t == 0) g_off[N_NODES] = g_total;
}

__global__ void fill_kernel(const void* __restrict__ eidx) {
    int e = blockIdx.x * blockDim.x + threadIdx.x;
    if (e < N_EDGES) {
        int d = load_idx(eidx, N_EDGES + e, g_is64);
        int pos = atomicAdd(&g_fill[d], 1);
        g_elist[pos] = e;
    }
}

// ---------------- per-node accumulation (warp per node) ----------------
__global__ void accum_kernel(const float* __restrict__ ns,
                             const void* __restrict__ eidx,
                             const void* __restrict__ etype,
                             const float* __restrict__ eb) {
    int w = (blockIdx.x * blockDim.x + threadIdx.x) >> 5;
    int lane = threadIdx.x & 31;
    if (w >= N_NODES) return;
    int is64 = g_is64;
    int s0 = g_off[w], s1 = g_off[w + 1];

    float4 a0 = {0,0,0,0}, a1 = a0, a2 = a0, a3 = a0;
    int c0 = 0, c1 = 0, c2 = 0, c3 = 0;

    for (int base = s0; base < s1; base += 32) {
        int nn = min(32, s1 - base);
        int src = 0, t = 0;
        if (lane < nn) {
            int eid = g_elist[base + lane];
            src = load_idx(eidx, eid, is64);
            t = load_idx(etype, eid, is64) & (NT - 1);
        }
        for (int j = 0; j < nn; j++) {
            int s  = __shfl_sync(0xffffffffu, src, j);
            int tt = __shfl_sync(0xffffffffu, t, j);
            float4 v = *(const float4*)(ns + (size_t)s * HID + 4 * lane);
            if (tt == 0)      { a0.x += v.x; a0.y += v.y; a0.z += v.z; a0.w += v.w; c0++; }
            else if (tt == 1) { a1.x += v.x; a1.y += v.y; a1.z += v.z; a1.w += v.w; c1++; }
            else if (tt == 2) { a2.x += v.x; a2.y += v.y; a2.z += v.z; a2.w += v.w; c2++; }
            else              { a3.x += v.x; a3.y += v.y; a3.z += v.z; a3.w += v.w; c3++; }
        }
    }

    size_t row = (size_t)w * HID + 4 * lane;
    *(float4*)(g_aggT + 0 * (size_t)N_NODES * HID + row) = a0;
    *(float4*)(g_aggT + 1 * (size_t)N_NODES * HID + row) = a1;
    *(float4*)(g_aggT + 2 * (size_t)N_NODES * HID + row) = a2;
    *(float4*)(g_aggT + 3 * (size_t)N_NODES * HID + row) = a3;

    float4 b0 = *(const float4*)(eb + 0 * HID + 4 * lane);
    float4 b1 = *(const float4*)(eb + 1 * HID + 4 * lane);
    float4 b2 = *(const float4*)(eb + 2 * HID + 4 * lane);
    float4 b3 = *(const float4*)(eb + 3 * HID + 4 * lane);
    float4 r;
    r.x = c0 * b0.x + c1 * b1.x + c2 * b2.x + c3 * b3.x;
    r.y = c0 * b0.y + c1 * b1.y + c2 * b2.y + c3 * b3.y;
    r.z = c0 * b0.z + c1 * b1.z + c2 * b2.z + c3 * b3.z;
    r.w = c0 * b0.w + c1 * b1.w + c2 * b2.w + c3 * b3.w;
    *(float4*)(g_agg + row) = r;
}

// ---------------- WMMA tf32 GEMM over slices (pre-rounded staging) ----------------
// slice s: [0,4)   agg type t : in=aggT[t], W=Wt[t],   out: red.add -> g_agg
//          [4,7)   gh gate g  : in=ns,      W=WhhT[g], out: g_gh (+bhh)
//          [7,10)  gi gate g  : in=g_agg,   W=WihT[g], out: g_gi (+bih)
__global__ void wgemm_kernel(const float* __restrict__ ns,
                             const float* __restrict__ bih,
                             const float* __restrict__ bhh,
                             int slice_base) {
    extern __shared__ float smem[];
    float* sA = smem;                 // [128][LDA]
    float* sB = smem + 128 * LDA;     // [128][LDA]  (k-major)

    int s = slice_base + blockIdx.y;
    const float* in; const float* W;
    float* outp = nullptr; const float* bias = nullptr;
    int colbase = 0, mode;
    if (s < NT) {
        in = g_aggT + (size_t)s * N_NODES * HID; W = g_Wt + s * HID * HID; mode = 0;
    } else if (s < NT + 3) {
        int g = s - NT;
        in = ns; W = g_WhhT + g * HID * HID; outp = g_gh; bias = bhh + g * HID;
        colbase = g * HID; mode = 1;
    } else {
        int g = s - NT - 3;
        in = g_agg; W = g_WihT + g * HID * HID; outp = g_gi; bias = bih + g * HID;
        colbase = g * HID; mode = 1;
    }

    int row0 = blockIdx.x * 128;
    int m = min(128, N_NODES - row0);

    // stage B (weights, k-major) and A (input rows) into SMEM, tf32-rounded
    for (int i = threadIdx.x; i < HID * HID / 4; i += blockDim.x) {
        int k = i >> 5, j4 = i & 31;
        *(float4*)(sB + k * LDA + 4 * j4) = round4(*(const float4*)(W + k * HID + 4 * j4));
    }
    for (int i = threadIdx.x; i < 128 * HID / 4; i += blockDim.x) {
        int r = i >> 5, c4 = i & 31;
        float4 v = make_float4(0.f, 0.f, 0.f, 0.f);
        if (r < m) v = round4(*(const float4*)(in + (size_t)(row0 + r) * HID + 4 * c4));
        *(float4*)(sA + r * LDA + 4 * c4) = v;
    }
    __syncthreads();

    int warp = threadIdx.x >> 5;
    int wr = warp >> 2;   // 0..1 : rows 64*wr..
    int wc = warp & 3;    // 0..3 : cols 32*wc..

    wmma::fragment<wmma::accumulator, 16, 16, 8, float> acc[4][2];
    #pragma unroll
    for (int a = 0; a < 4; a++)
        #pragma unroll
        for (int b = 0; b < 2; b++)
            wmma::fill_fragment(acc[a][b], 0.0f);

    #pragma unroll
    for (int k = 0; k < HID; k += 8) {
        wmma::fragment<wmma::matrix_a, 16, 16, 8, wmma::precision::tf32, wmma::row_major> af[4];
        wmma::fragment<wmma::matrix_b, 16, 16, 8, wmma::precision::tf32, wmma::row_major> bf[2];
        #pragma unroll
        for (int a = 0; a < 4; a++)
            wmma::load_matrix_sync(af[a], sA + (64 * wr + 16 * a) * LDA + k, LDA);
        #pragma unroll
        for (int b = 0; b < 2; b++)
            wmma::load_matrix_sync(bf[b], sB + k * LDA + 32 * wc + 16 * b, LDA);
        #pragma unroll
        for (int a = 0; a < 4; a++)
            #pragma unroll
            for (int b = 0; b < 2; b++)
                wmma::mma_sync(acc[a][b], af[a], bf[b], acc[a][b]);
    }
    __syncthreads();

    #pragma unroll
    for (int a = 0; a < 4; a++)
        #pragma unroll
        for (int b = 0; b < 2; b++)
            wmma::store_matrix_sync(sA + (64 * wr + 16 * a) * LDA + 32 * wc + 16 * b,
                                    acc[a][b], LDA, wmma::mem_row_major);
    __syncthreads();

    for (int i = threadIdx.x; i < 128 * 32; i += blockDim.x) {
        int r = i >> 5, c4 = i & 31;
        if (r < m) {
            float4 v = *(float4*)(sA + r * LDA + 4 * c4);
            if (mode == 0) {
                red_add_v4(g_agg + (size_t)(row0 + r) * HID + 4 * c4, v);
            } else {
                float4 bb = *(const float4*)(bias + 4 * c4);
                v.x += bb.x; v.y += bb.y; v.z += bb.z; v.w += bb.w;
                *(float4*)(outp + (size_t)(row0 + r) * (3 * HID) + colbase + 4 * c4) = v;
            }
        }
    }
}

// ---------------- GRU pointwise finish ----------------
__global__ void gru_final_kernel(const float* __restrict__ ns, float* __restrict__ out) {
    int idx = blockIdx.x * blockDim.x + threadIdx.x;
    if (idx >= N_NODES * HID) return;
    int n = idx >> 7;
    int j = idx & 127;
    size_t b = (size_t)n * (3 * HID) + j;
    float ir = g_gi[b], iz = g_gi[b + 128], inn = g_gi[b + 256];
    float hr = g_gh[b], hz = g_gh[b + 128], hn = g_gh[b + 256];
    float r = 1.0f / (1.0f + __expf(-(ir + hr)));
    float z = 1.0f / (1.0f + __expf(-(iz + hz)));
    float nn = tanhf(inn + r * hn);
    out[idx] = (1.0f - z) * nn + z * ns[idx];
}

// ---------------- launch ----------------
extern "C" void kernel_launch(void* const* d_in, const int* in_sizes, int n_in,
                              void* d_out, int out_size) {
    const float* ns    = (const float*)d_in[0];
    const void*  eidx  = d_in[1];
    const void*  etype = d_in[2];
    const float* eW    = (const float*)d_in[3];
    const float* eb    = (const float*)d_in[4];
    const float* wih   = (const float*)d_in[5];
    const float* whh   = (const float*)d_in[6];
    const float* bih   = (const float*)d_in[7];
    const float* bhh   = (const float*)d_in[8];
    float* out = (float*)d_out;

    const int GSMEM = 2 * 128 * LDA * (int)sizeof(float); // 139264 B
    cudaFuncSetAttribute(wgemm_kernel, cudaFuncAttributeMaxDynamicSharedMemorySize, GSMEM);

    const int SCAN_BLOCKS = (N_NODES + 255) / 256; // 196
    const int GEMM_BLOCKS = (N_NODES + 127) / 128; // 391

    detect_kernel<<<1, 1>>>((const int*)eidx);
    prep_kernel<<<(NT * HID * HID + 255) / 256, 256>>>(eW, wih, whh);
    hist_kernel<<<(N_EDGES + 255) / 256, 256>>>(eidx);
    scan_p1<<<SCAN_BLOCKS, 256>>>();
    scan_p2<<<1, 256>>>(SCAN_BLOCKS);
    scan_p3<<<SCAN_BLOCKS, 256>>>();
    fill_kernel<<<(N_EDGES + 255) / 256, 256>>>(eidx);
    accum_kernel<<<(N_NODES * 32 + 255) / 256, 256>>>(ns, eidx, etype, eb);
    wgemm_kernel<<<dim3(GEMM_BLOCKS, 7), 256, GSMEM>>>(ns, bih, bhh, 0);  // 4 agg + 3 gh
    wgemm_kernel<<<dim3(GEMM_BLOCKS, 3), 256, GSMEM>>>(ns, bih, bhh, 7);  // 3 gi
    gru_final_kernel<<<(N_NODES * HID + 255) / 256, 256>>>(ns, out);
}

// round 13
// speedup vs baseline: 2.1035x; 1.0394x over previous
#include <cuda_runtime.h>
#include <cstdint>
#include <mma.h>
using namespace nvcuda;

#define N_NODES 50000
#define N_EDGES 625000
#define HID 128
#define NT 4
#define LDA 136   // 128 + 8 pad (floats)

// ---------------- scratch (device globals) ----------------
__device__ float g_agg[N_NODES * HID];
__device__ float g_aggT[(size_t)N_NODES * 512];   // cat layout: [n][t*128+d]
__device__ float g_WcatT[512 * HID];              // [k'=t*128+k][j] = eW[t][j][k]
__device__ float g_WihT[3 * HID * HID];           // [g][k][j] = wih[g*128+j][k]
__device__ float g_WhhT[3 * HID * HID];
__device__ float g_gi[(size_t)N_NODES * 3 * HID];
__device__ float g_gh[(size_t)N_NODES * 3 * HID];
__device__ int   g_deg[N_NODES];
__device__ int   g_off[N_NODES + 1];
__device__ int   g_fill[N_NODES];
__device__ int   g_elist[N_EDGES];
__device__ int   g_bsum[256];
__device__ int   g_bbase[256];
__device__ int   g_total;
__device__ int   g_is64;

__device__ __forceinline__ int load_idx(const void* p, int i, int is64) {
    if (is64) return (int)((const long long*)p)[i];
    return ((const int*)p)[i];
}

__device__ __forceinline__ void red_add_v4(float* ptr, float4 v) {
    asm volatile("red.global.add.v4.f32 [%0], {%1,%2,%3,%4};"
                 :: "l"(ptr), "f"(v.x), "f"(v.y), "f"(v.z), "f"(v.w) : "memory");
}

__device__ __forceinline__ float f2tf32f(float x) {
    uint32_t o;
    asm("cvt.rna.tf32.f32 %0, %1;" : "=r"(o) : "f"(x));
    return __uint_as_float(o);
}

__device__ __forceinline__ float4 round4(float4 v) {
    return make_float4(f2tf32f(v.x), f2tf32f(v.y), f2tf32f(v.z), f2tf32f(v.w));
}

// ---------------- dtype detect ----------------
__global__ void detect_kernel(const int* __restrict__ ei_as_i32) {
    int ok = 1;
    for (int i = 0; i < 64; i++)
        if (ei_as_i32[2 * i + 1] != 0) ok = 0;
    g_is64 = ok;
}

// ---------------- prep: weight transposes + zero deg ----------------
__global__ void prep_kernel(const float* __restrict__ eW,
                            const float* __restrict__ wih,
                            const float* __restrict__ whh) {
    int i = blockIdx.x * blockDim.x + threadIdx.x;
    if (i < 512 * HID) {                 // WcatT[k'][j]
        int kp = i >> 7, j = i & 127;
        g_WcatT[i] = eW[(kp >> 7) * 16384 + j * HID + (kp & 127)];
    }
    if (i < 3 * HID * HID) {
        int g = i >> 14, r = i & 16383, k = r >> 7, j = r & 127;
        g_WihT[i] = wih[((g << 7) + j) * HID + k];
        g_WhhT[i] = whh[((g << 7) + j) * HID + k];
    }
    if (i < N_NODES) g_deg[i] = 0;
}

// ---------------- CSR by destination ----------------
__global__ void hist_kernel(const void* __restrict__ eidx) {
    int e = blockIdx.x * blockDim.x + threadIdx.x;
    if (e < N_EDGES) {
        int d = load_idx(eidx, N_EDGES + e, g_is64);
        atomicAdd(&g_deg[d], 1);
    }
}

__global__ void scan_p1() {
    __shared__ int sh[256];
    int i = blockIdx.x * 256 + threadIdx.x;
    sh[threadIdx.x] = (i < N_NODES) ? g_deg[i] : 0;
    __syncthreads();
    for (int d = 128; d > 0; d >>= 1) {
        if (threadIdx.x < d) sh[threadIdx.x] += sh[threadIdx.x + d];
        __syncthreads();
    }
    if (threadIdx.x == 0) g_bsum[blockIdx.x] = sh[0];
}

__global__ void scan_p2(int nblocks) {
    __shared__ int sh[256];
    int t = threadIdx.x;
    int v = (t < nblocks) ? g_bsum[t] : 0;
    sh[t] = v;
    __syncthreads();
    for (int d = 1; d < 256; d <<= 1) {
        int x = (t >= d) ? sh[t - d] : 0;
        __syncthreads();
        sh[t] += x;
        __syncthreads();
    }
    g_bbase[t] = sh[t] - v;
    if (t == 255) g_total = sh[255];
}

__global__ void scan_p3() {
    __shared__ int sh[256];
    int t = threadIdx.x;
    int i = blockIdx.x * 256 + t;
    int v = (i < N_NODES) ? g_deg[i] : 0;
    sh[t] = v;
    __syncthreads();
    for (int d = 1; d < 256; d <<= 1) {
        int x = (t >= d) ? sh[t - d] : 0;
        __syncthreads();
        sh[t] += x;
        __syncthreads();
    }
    if (i < N_NODES) {
        int o = g_bbase[blockIdx.x] + sh[t] - v;
        g_off[i] = o;
        g_fill[i] = o;
    }
    if (blockIdx.x == 0 && t == 0) g_off[N_NODES] = g_total;
}

__global__ void fill_kernel(const void* __restrict__ eidx) {
    int e = blockIdx.x * blockDim.x + threadIdx.x;
    if (e < N_EDGES) {
        int d = load_idx(eidx, N_EDGES + e, g_is64);
        int pos = atomicAdd(&g_fill[d], 1);
        g_elist[pos] = e;
    }
}

// ---------------- per-node accumulation (warp per node) ----------------
__global__ void accum_kernel(const float* __restrict__ ns,
                             const void* __restrict__ eidx,
                             const void* __restrict__ etype,
                             const float* __restrict__ eb) {
    int w = (blockIdx.x * blockDim.x + threadIdx.x) >> 5;
    int lane = threadIdx.x & 31;
    if (w >= N_NODES) return;
    int is64 = g_is64;
    int s0 = g_off[w], s1 = g_off[w + 1];

    float4 a0 = {0,0,0,0}, a1 = a0, a2 = a0, a3 = a0;
    int c0 = 0, c1 = 0, c2 = 0, c3 = 0;

    for (int base = s0; base < s1; base += 32) {
        int nn = min(32, s1 - base);
        int src = 0, t = 0;
        if (lane < nn) {
            int eid = g_elist[base + lane];
            src = load_idx(eidx, eid, is64);
            t = load_idx(etype, eid, is64) & (NT - 1);
        }
        for (int j = 0; j < nn; j++) {
            int s  = __shfl_sync(0xffffffffu, src, j);
            int tt = __shfl_sync(0xffffffffu, t, j);
            float4 v = *(const float4*)(ns + (size_t)s * HID + 4 * lane);
            if (tt == 0)      { a0.x += v.x; a0.y += v.y; a0.z += v.z; a0.w += v.w; c0++; }
            else if (tt == 1) { a1.x += v.x; a1.y += v.y; a1.z += v.z; a1.w += v.w; c1++; }
            else if (tt == 2) { a2.x += v.x; a2.y += v.y; a2.z += v.z; a2.w += v.w; c2++; }
            else              { a3.x += v.x; a3.y += v.y; a3.z += v.z; a3.w += v.w; c3++; }
        }
    }

    size_t row = (size_t)w * 512 + 4 * lane;   // cat layout
    *(float4*)(g_aggT + row +   0) = a0;
    *(float4*)(g_aggT + row + 128) = a1;
    *(float4*)(g_aggT + row + 256) = a2;
    *(float4*)(g_aggT + row + 384) = a3;

    float4 b0 = *(const float4*)(eb + 0 * HID + 4 * lane);
    float4 b1 = *(const float4*)(eb + 1 * HID + 4 * lane);
    float4 b2 = *(const float4*)(eb + 2 * HID + 4 * lane);
    float4 b3 = *(const float4*)(eb + 3 * HID + 4 * lane);
    float4 r;
    r.x = c0 * b0.x + c1 * b1.x + c2 * b2.x + c3 * b3.x;
    r.y = c0 * b0.y + c1 * b1.y + c2 * b2.y + c3 * b3.y;
    r.z = c0 * b0.z + c1 * b1.z + c2 * b2.z + c3 * b3.z;
    r.w = c0 * b0.w + c1 * b1.w + c2 * b2.w + c3 * b3.w;
    *(float4*)(g_agg + (size_t)w * HID + 4 * lane) = r;   // count-bias row
}

// ---------------- WMMA tf32 GEMMs: 512 threads, M-tile 256, 4x4 warps ----------------
// mode 0: agg   = aggT_cat[50000x512] @ WcatT  -> red.add into g_agg (4 k-chunks)
// mode 1: g_gh  = ns    @ WhhT (3 gates, N-chunks, direct fragment store, no bias)
// mode 2: g_gi  = g_agg @ WihT (3 gates, direct store, no bias)
__global__ void __launch_bounds__(512, 1)
wgemm_kernel(const float* __restrict__ ns, int mode_base) {
    extern __shared__ float smem[];
    float* sA = smem;                 // [256][LDA]
    float* sB = smem + 256 * LDA;     // [128][LDA]

    int mode = mode_base + blockIdx.y;
    int row0 = blockIdx.x * 256;
    int m = min(256, N_NODES - row0);

    int tid = threadIdx.x;
    int warp = tid >> 5;
    int wr = warp >> 2;   // 0..3 : rows 64*wr
    int wc = warp & 3;    // 0..3 : cols 32*wc

    if (mode == 0) {
        wmma::fragment<wmma::accumulator, 16, 16, 8, float> acc[4][2];
        #pragma unroll
        for (int a = 0; a < 4; a++)
            #pragma unroll
            for (int b = 0; b < 2; b++)
                wmma::fill_fragment(acc[a][b], 0.0f);

        for (int c = 0; c < 4; c++) {
            __syncthreads();
            for (int i = tid; i < 256 * 32; i += 512) {
                int r = i >> 5, c4 = i & 31;
                float4 v = make_float4(0.f, 0.f, 0.f, 0.f);
                if (r < m)
                    v = round4(*(const float4*)(g_aggT + (size_t)(row0 + r) * 512 + c * 128 + 4 * c4));
                *(float4*)(sA + r * LDA + 4 * c4) = v;
            }
            for (int i = tid; i < 128 * 32; i += 512) {
                int k = i >> 5, j4 = i & 31;
                *(float4*)(sB + k * LDA + 4 * j4) =
                    round4(*(const float4*)(g_WcatT + (c * 128 + k) * HID + 4 * j4));
            }
            __syncthreads();

            #pragma unroll
            for (int k = 0; k < HID; k += 8) {
                wmma::fragment<wmma::matrix_a, 16, 16, 8, wmma::precision::tf32, wmma::row_major> af[4];
                wmma::fragment<wmma::matrix_b, 16, 16, 8, wmma::precision::tf32, wmma::row_major> bf[2];
                #pragma unroll
                for (int a = 0; a < 4; a++)
                    wmma::load_matrix_sync(af[a], sA + (64 * wr + 16 * a) * LDA + k, LDA);
                #pragma unroll
                for (int b = 0; b < 2; b++)
                    wmma::load_matrix_sync(bf[b], sB + k * LDA + 32 * wc + 16 * b, LDA);
                #pragma unroll
                for (int a = 0; a < 4; a++)
                    #pragma unroll
                    for (int b = 0; b < 2; b++)
                        wmma::mma_sync(acc[a][b], af[a], bf[b], acc[a][b]);
            }
        }
        __syncthreads();
        #pragma unroll
        for (int a = 0; a < 4; a++)
            #pragma unroll
            for (int b = 0; b < 2; b++)
                wmma::store_matrix_sync(sA + (64 * wr + 16 * a) * LDA + 32 * wc + 16 * b,
                                        acc[a][b], LDA, wmma::mem_row_major);
        __syncthreads();
        for (int i = tid; i < 256 * 32; i += 512) {
            int r = i >> 5, c4 = i & 31;
            if (r < m)
                red_add_v4(g_agg + (size_t)(row0 + r) * HID + 4 * c4,
                           *(float4*)(sA + r * LDA + 4 * c4));
        }
    } else {
        const float* inA = (mode == 1) ? ns : g_agg;
        const float* WT  = (mode == 1) ? g_WhhT : g_WihT;
        float* outp      = (mode == 1) ? g_gh : g_gi;

        // stage A once
        for (int i = tid; i < 256 * 32; i += 512) {
            int r = i >> 5, c4 = i & 31;
            float4 v = make_float4(0.f, 0.f, 0.f, 0.f);
            if (r < m)
                v = round4(*(const float4*)(inA + (size_t)(row0 + r) * HID + 4 * c4));
            *(float4*)(sA + r * LDA + 4 * c4) = v;
        }

        for (int g = 0; g < 3; g++) {
            __syncthreads();   // A staged / previous chunk's sB reads done
            for (int i = tid; i < 128 * 32; i += 512) {
                int k = i >> 5, j4 = i & 31;
                *(float4*)(sB + k * LDA + 4 * j4) =
                    round4(*(const float4*)(WT + g * HID * HID + k * HID + 4 * j4));
            }
            __syncthreads();

            wmma::fragment<wmma::accumulator, 16, 16, 8, float> acc[4][2];
            #pragma unroll
            for (int a = 0; a < 4; a++)
                #pragma unroll
                for (int b = 0; b < 2; b++)
                    wmma::fill_fragment(acc[a][b], 0.0f);

            #pragma unroll
            for (int k = 0; k < HID; k += 8) {
                wmma::fragment<wmma::matrix_a, 16, 16, 8, wmma::precision::tf32, wmma::row_major> af[4];
                wmma::fragment<wmma::matrix_b, 16, 16, 8, wmma::precision::tf32, wmma::row_major> bf[2];
                #pragma unroll
                for (int a = 0; a < 4; a++)
                    wmma::load_matrix_sync(af[a], sA + (64 * wr + 16 * a) * LDA + k, LDA);
                #pragma unroll
                for (int b = 0; b < 2; b++)
                    wmma::load_matrix_sync(bf[b], sB + k * LDA + 32 * wc + 16 * b, LDA);
                #pragma unroll
                for (int a = 0; a < 4; a++)
                    #pragma unroll
                    for (int b = 0; b < 2; b++)
                        wmma::mma_sync(acc[a][b], af[a], bf[b], acc[a][b]);
            }

            // direct fragment store to global (row stride 384); 50000 % 16 == 0,
            // so fragments never straddle the m boundary.
            #pragma unroll
            for (int a = 0; a < 4; a++) {
                int fr = 64 * wr + 16 * a;
                if (fr < m) {
                    #pragma unroll
                    for (int b = 0; b < 2; b++)
                        wmma::store_matrix_sync(
                            outp + (size_t)(row0 + fr) * 384 + g * HID + 32 * wc + 16 * b,
                            acc[a][b], 384, wmma::mem_row_major);
                }
            }
        }
    }
}

// ---------------- GRU pointwise finish (biases folded in here) ----------------
__global__ void gru_final_kernel(const float* __restrict__ ns,
                                 const float* __restrict__ bih,
                                 const float* __restrict__ bhh,
                                 float* __restrict__ out) {
    int idx = blockIdx.x * blockDim.x + threadIdx.x;
    if (idx >= N_NODES * HID) return;
    int n = idx >> 7;
    int j = idx & 127;
    size_t b = (size_t)n * (3 * HID) + j;
    float ir = g_gi[b] + bih[j],        hr = g_gh[b] + bhh[j];
    float iz = g_gi[b + 128] + bih[j + 128], hz = g_gh[b + 128] + bhh[j + 128];
    float inn = g_gi[b + 256] + bih[j + 256];
    float hn  = g_gh[b + 256] + bhh[j + 256];
    float r = 1.0f / (1.0f + __expf(-(ir + hr)));
    float z = 1.0f / (1.0f + __expf(-(iz + hz)));
    float nn = tanhf(inn + r * hn);
    out[idx] = (1.0f - z) * nn + z * ns[idx];
}

// ---------------- launch ----------------
extern "C" void kernel_launch(void* const* d_in, const int* in_sizes, int n_in,
                              void* d_out, int out_size) {
    const float* ns    = (const float*)d_in[0];
    const void*  eidx  = d_in[1];
    const void*  etype = d_in[2];
    const float* eW    = (const float*)d_in[3];
    const float* eb    = (const float*)d_in[4];
    const float* wih   = (const float*)d_in[5];
    const float* whh   = (const float*)d_in[6];
    const float* bih   = (const float*)d_in[7];
    const float* bhh   = (const float*)d_in[8];
    float* out = (float*)d_out;

    const int GSMEM = (256 * LDA + 128 * LDA) * (int)sizeof(float); // 208896 B
    cudaFuncSetAttribute(wgemm_kernel, cudaFuncAttributeMaxDynamicSharedMemorySize, GSMEM);

    const int SCAN_BLOCKS = (N_NODES + 255) / 256; // 196
    const int GEMM_BLOCKS = (N_NODES + 255) / 256; // 196

    detect_kernel<<<1, 1>>>((const int*)eidx);
    prep_kernel<<<(512 * HID + 255) / 256, 256>>>(eW, wih, whh);
    hist_kernel<<<(N_EDGES + 255) / 256, 256>>>(eidx);
    scan_p1<<<SCAN_BLOCKS, 256>>>();
    scan_p2<<<1, 256>>>(SCAN_BLOCKS);
    scan_p3<<<SCAN_BLOCKS, 256>>>();
    fill_kernel<<<(N_EDGES + 255) / 256, 256>>>(eidx);
    accum_kernel<<<(N_NODES * 32 + 255) / 256, 256>>>(ns, eidx, etype, eb);
    wgemm_kernel<<<dim3(GEMM_BLOCKS, 2), 512, GSMEM>>>(ns, 0);  // mode 0 (agg) + mode 1 (gh)
    wgemm_kernel<<<dim3(GEMM_BLOCKS, 1), 512, GSMEM>>>(ns, 2);  // mode 2 (gi)
    gru_final_kernel<<<(N_NODES * HID + 255) / 256, 256>>>(ns, bih, bhh, out);
}

// round 17
// speedup vs baseline: 3.7030x; 1.7604x over previous
#include <cuda_runtime.h>
#include <cstdint>
#include <cuda_fp16.h>
#include <mma.h>
using namespace nvcuda;

#define N_NODES 50000
#define N_EDGES 625000
#define HID 128
#define NT 4
#define LDAH 136   // halves: 272B row stride, 16B-aligned, conflict-free for ldmatrix

// ---------------- scratch (device globals) ----------------
__device__ float  g_cb[N_NODES * HID];                  // count-bias rows (accum)
__device__ float  g_aggG[N_NODES * HID];                // GEMM part of agg (mode 0 out)
__device__ __half g_aggT_h[(size_t)N_NODES * 512];      // per-type x sums, fp16 cat layout
__device__ __half g_WcatT_h[512 * HID];                 // [k'=t*128+k][j] = eW[t][j][k]
__device__ __half g_WihT_h[3 * HID * HID];              // [g][k][j]
__device__ __half g_WhhT_h[3 * HID * HID];
__device__ float  g_gi[(size_t)N_NODES * 3 * HID];
__device__ float  g_gh[(size_t)N_NODES * 3 * HID];
__device__ int    g_deg[N_NODES];
__device__ int    g_off[N_NODES + 1];
__device__ int    g_fill[N_NODES];
__device__ int    g_elist[N_EDGES];
__device__ int    g_bsum[256];
__device__ int    g_bbase[256];
__device__ int    g_total;
__device__ int    g_is64;

__device__ __forceinline__ int load_idx(const void* p, int i, int is64) {
    if (is64) return (int)((const long long*)p)[i];
    return ((const int*)p)[i];
}

// ---------------- dtype detect ----------------
__global__ void detect_kernel(const int* __restrict__ ei_as_i32) {
    int ok = 1;
    for (int i = 0; i < 64; i++)
        if (ei_as_i32[2 * i + 1] != 0) ok = 0;
    g_is64 = ok;
}

// ---------------- prep: fp16 weight transposes + zero deg ----------------
__global__ void prep_kernel(const float* __restrict__ eW,
                            const float* __restrict__ wih,
                            const float* __restrict__ whh) {
    int i = blockIdx.x * blockDim.x + threadIdx.x;
    if (i < 512 * HID) {                 // WcatT[k'][j]
        int kp = i >> 7, j = i & 127;
        g_WcatT_h[i] = __float2half_rn(eW[(kp >> 7) * 16384 + j * HID + (kp & 127)]);
    }
    if (i < 3 * HID * HID) {
        int g = i >> 14, r = i & 16383, k = r >> 7, j = r & 127;
        g_WihT_h[i] = __float2half_rn(wih[((g << 7) + j) * HID + k]);
        g_WhhT_h[i] = __float2half_rn(whh[((g << 7) + j) * HID + k]);
    }
    if (i < N_NODES) g_deg[i] = 0;
}

// ---------------- CSR by destination ----------------
__global__ void hist_kernel(const void* __restrict__ eidx) {
    int e = blockIdx.x * blockDim.x + threadIdx.x;
    if (e < N_EDGES) {
        int d = load_idx(eidx, N_EDGES + e, g_is64);
        atomicAdd(&g_deg[d], 1);
    }
}

__global__ void scan_p1() {
    __shared__ int sh[256];
    int i = blockIdx.x * 256 + threadIdx.x;
    sh[threadIdx.x] = (i < N_NODES) ? g_deg[i] : 0;
    __syncthreads();
    for (int d = 128; d > 0; d >>= 1) {
        if (threadIdx.x < d) sh[threadIdx.x] += sh[threadIdx.x + d];
        __syncthreads();
    }
    if (threadIdx.x == 0) g_bsum[blockIdx.x] = sh[0];
}

__global__ void scan_p2(int nblocks) {
    __shared__ int sh[256];
    int t = threadIdx.x;
    int v = (t < nblocks) ? g_bsum[t] : 0;
    sh[t] = v;
    __syncthreads();
    for (int d = 1; d < 256; d <<= 1) {
        int x = (t >= d) ? sh[t - d] : 0;
        __syncthreads();
        sh[t] += x;
        __syncthreads();
    }
    g_bbase[t] = sh[t] - v;
    if (t == 255) g_total = sh[255];
}

__global__ void scan_p3() {
    __shared__ int sh[256];
    int t = threadIdx.x;
    int i = blockIdx.x * 256 + t;
    int v = (i < N_NODES) ? g_deg[i] : 0;
    sh[t] = v;
    __syncthreads();
    for (int d = 1; d < 256; d <<= 1) {
        int x = (t >= d) ? sh[t - d] : 0;
        __syncthreads();
        sh[t] += x;
        __syncthreads();
    }
    if (i < N_NODES) {
        int o = g_bbase[blockIdx.x] + sh[t] - v;
        g_off[i] = o;
        g_fill[i] = o;
    }
    if (blockIdx.x == 0 && t == 0) g_off[N_NODES] = g_total;
}

__global__ void fill_kernel(const void* __restrict__ eidx) {
    int e = blockIdx.x * blockDim.x + threadIdx.x;
    if (e < N_EDGES) {
        int d = load_idx(eidx, N_EDGES + e, g_is64);
        int pos = atomicAdd(&g_fill[d], 1);
        g_elist[pos] = e;
    }
}

// ---------------- per-node accumulation (warp per node) ----------------
__global__ void accum_kernel(const float* __restrict__ ns,
                             const void* __restrict__ eidx,
                             const void* __restrict__ etype,
                             const float* __restrict__ eb) {
    int w = (blockIdx.x * blockDim.x + threadIdx.x) >> 5;
    int lane = threadIdx.x & 31;
    if (w >= N_NODES) return;
    int is64 = g_is64;
    int s0 = g_off[w], s1 = g_off[w + 1];

    float4 a0 = {0,0,0,0}, a1 = a0, a2 = a0, a3 = a0;
    int c0 = 0, c1 = 0, c2 = 0, c3 = 0;

    for (int base = s0; base < s1; base += 32) {
        int nn = min(32, s1 - base);
        int src = 0, t = 0;
        if (lane < nn) {
            int eid = g_elist[base + lane];
            src = load_idx(eidx, eid, is64);
            t = load_idx(etype, eid, is64) & (NT - 1);
        }
        for (int j = 0; j < nn; j++) {
            int s  = __shfl_sync(0xffffffffu, src, j);
            int tt = __shfl_sync(0xffffffffu, t, j);
            float4 v = *(const float4*)(ns + (size_t)s * HID + 4 * lane);
            if (tt == 0)      { a0.x += v.x; a0.y += v.y; a0.z += v.z; a0.w += v.w; c0++; }
            else if (tt == 1) { a1.x += v.x; a1.y += v.y; a1.z += v.z; a1.w += v.w; c1++; }
            else if (tt == 2) { a2.x += v.x; a2.y += v.y; a2.z += v.z; a2.w += v.w; c2++; }
            else              { a3.x += v.x; a3.y += v.y; a3.z += v.z; a3.w += v.w; c3++; }
        }
    }

    // store per-type sums as fp16 (cat layout)
    size_t row = (size_t)w * 512 + 4 * lane;
    *(__half2*)(g_aggT_h + row +   0) = __floats2half2_rn(a0.x, a0.y);
    *(__half2*)(g_aggT_h + row +   2) = __floats2half2_rn(a0.z, a0.w);
    *(__half2*)(g_aggT_h + row + 128) = __floats2half2_rn(a1.x, a1.y);
    *(__half2*)(g_aggT_h + row + 130) = __floats2half2_rn(a1.z, a1.w);
    *(__half2*)(g_aggT_h + row + 256) = __floats2half2_rn(a2.x, a2.y);
    *(__half2*)(g_aggT_h + row + 258) = __floats2half2_rn(a2.z, a2.w);
    *(__half2*)(g_aggT_h + row + 384) = __floats2half2_rn(a3.x, a3.y);
    *(__half2*)(g_aggT_h + row + 386) = __floats2half2_rn(a3.z, a3.w);

    float4 b0 = *(const float4*)(eb + 0 * HID + 4 * lane);
    float4 b1 = *(const float4*)(eb + 1 * HID + 4 * lane);
    float4 b2 = *(const float4*)(eb + 2 * HID + 4 * lane);
    float4 b3 = *(const float4*)(eb + 3 * HID + 4 * lane);
    float4 r;
    r.x = c0 * b0.x + c1 * b1.x + c2 * b2.x + c3 * b3.x;
    r.y = c0 * b0.y + c1 * b1.y + c2 * b2.y + c3 * b3.y;
    r.z = c0 * b0.z + c1 * b1.z + c2 * b2.z + c3 * b3.z;
    r.w = c0 * b0.w + c1 * b1.w + c2 * b2.w + c3 * b3.w;
    *(float4*)(g_cb + (size_t)w * HID + 4 * lane) = r;
}

// ---------------- WMMA fp16 GEMMs: 512 threads, M-tile 256, 4x4 warps ----------------
// mode 0: g_aggG = aggT_h[50000x512] @ WcatT_h   (4 k-chunks, direct store ldm=128)
// mode 1: g_gh   = fp16(ns)    @ WhhT_h (3 gates, direct store ldm=384)
// mode 2: g_gi   = fp16(aggG+cb) @ WihT_h (3 gates, direct store ldm=384)
__global__ void __launch_bounds__(512, 1)
wgemm_kernel(const float* __restrict__ ns, int mode_base) {
    extern __shared__ __half smh[];
    __half* sA = smh;                  // [256][LDAH]
    __half* sB = smh + 256 * LDAH;     // [128][LDAH]

    int mode = mode_base + blockIdx.y;
    int row0 = blockIdx.x * 256;
    int m = min(256, N_NODES - row0);

    int tid = threadIdx.x;
    int warp = tid >> 5;
    int wr = warp >> 2;   // 0..3 : rows 64*wr
    int wc = warp & 3;    // 0..3 : cols 32*wc

    if (mode == 0) {
        wmma::fragment<wmma::accumulator, 16, 16, 16, float> acc[4][2];
        #pragma unroll
        for (int a = 0; a < 4; a++)
            #pragma unroll
            for (int b = 0; b < 2; b++)
                wmma::fill_fragment(acc[a][b], 0.0f);

        for (int c = 0; c < 4; c++) {
            __syncthreads();
            // A chunk: fp16 copy from aggT_h (8B per thread-iter)
            for (int i = tid; i < 256 * 32; i += 512) {
                int r = i >> 5, c4 = i & 31;
                uint2 v = make_uint2(0u, 0u);
                if (r < m)
                    v = *(const uint2*)(g_aggT_h + (size_t)(row0 + r) * 512 + c * 128 + 4 * c4);
                *(uint2*)(sA + r * LDAH + 4 * c4) = v;
            }
            // B chunk: fp16 copy
            for (int i = tid; i < 128 * 32; i += 512) {
                int k = i >> 5, j4 = i & 31;
                *(uint2*)(sB + k * LDAH + 4 * j4) =
                    *(const uint2*)(g_WcatT_h + (c * 128 + k) * HID + 4 * j4);
            }
            __syncthreads();

            #pragma unroll
            for (int k = 0; k < HID; k += 16) {
                wmma::fragment<wmma::matrix_a, 16, 16, 16, __half, wmma::row_major> af[4];
                wmma::fragment<wmma::matrix_b, 16, 16, 16, __half, wmma::row_major> bf[2];
                #pragma unroll
                for (int a = 0; a < 4; a++)
                    wmma::load_matrix_sync(af[a], sA + (64 * wr + 16 * a) * LDAH + k, LDAH);
                #pragma unroll
                for (int b = 0; b < 2; b++)
                    wmma::load_matrix_sync(bf[b], sB + k * LDAH + 32 * wc + 16 * b, LDAH);
                #pragma unroll
                for (int a = 0; a < 4; a++)
                    #pragma unroll
                    for (int b = 0; b < 2; b++)
                        wmma::mma_sync(acc[a][b], af[a], bf[b], acc[a][b]);
            }
        }
        // direct store; 50000 % 16 == 0 so fragments never straddle m
        #pragma unroll
        for (int a = 0; a < 4; a++) {
            int fr = 64 * wr + 16 * a;
            if (fr < m) {
                #pragma unroll
                for (int b = 0; b < 2; b++)
                    wmma::store_matrix_sync(
                        g_aggG + (size_t)(row0 + fr) * HID + 32 * wc + 16 * b,
                        acc[a][b], HID, wmma::mem_row_major);
            }
        }
    } else {
        const __half* WT = (mode == 1) ? g_WhhT_h : g_WihT_h;
        float* outp      = (mode == 1) ? g_gh : g_gi;

        // stage A once (cvt fp32 -> fp16; mode 2 adds count-bias)
        for (int i = tid; i < 256 * 32; i += 512) {
            int r = i >> 5, c4 = i & 31;
            float4 v = make_float4(0.f, 0.f, 0.f, 0.f);
            if (r < m) {
                size_t o = (size_t)(row0 + r) * HID + 4 * c4;
                if (mode == 1) {
                    v = *(const float4*)(ns + o);
                } else {
                    float4 x = *(const float4*)(g_aggG + o);
                    float4 y = *(const float4*)(g_cb + o);
                    v = make_float4(x.x + y.x, x.y + y.y, x.z + y.z, x.w + y.w);
                }
            }
            __half* dst = sA + r * LDAH + 4 * c4;
            *(__half2*)(dst + 0) = __floats2half2_rn(v.x, v.y);
            *(__half2*)(dst + 2) = __floats2half2_rn(v.z, v.w);
        }

        for (int g = 0; g < 3; g++) {
            __syncthreads();
            for (int i = tid; i < 128 * 32; i += 512) {
                int k = i >> 5, j4 = i & 31;
                *(uint2*)(sB + k * LDAH + 4 * j4) =
                    *(const uint2*)(WT + g * HID * HID + k * HID + 4 * j4);
            }
            __syncthreads();

            wmma::fragment<wmma::accumulator, 16, 16, 16, float> acc[4][2];
            #pragma unroll
            for (int a = 0; a < 4; a++)
                #pragma unroll
                for (int b = 0; b < 2; b++)
                    wmma::fill_fragment(acc[a][b], 0.0f);

            #pragma unroll
            for (int k = 0; k < HID; k += 16) {
                wmma::fragment<wmma::matrix_a, 16, 16, 16, __half, wmma::row_major> af[4];
                wmma::fragment<wmma::matrix_b, 16, 16, 16, __half, wmma::row_major> bf[2];
                #pragma unroll
                for (int a = 0; a < 4; a++)
                    wmma::load_matrix_sync(af[a], sA + (64 * wr + 16 * a) * LDAH + k, LDAH);
                #pragma unroll
                for (int b = 0; b < 2; b++)
                    wmma::load_matrix_sync(bf[b], sB + k * LDAH + 32 * wc + 16 * b, LDAH);
                #pragma unroll
                for (int a = 0; a < 4; a++)
                    #pragma unroll
                    for (int b = 0; b < 2; b++)
                        wmma::mma_sync(acc[a][b], af[a], bf[b], acc[a][b]);
            }

            #pragma unroll
            for (int a = 0; a < 4; a++) {
                int fr = 64 * wr + 16 * a;
                if (fr < m) {
                    #pragma unroll
                    for (int b = 0; b < 2; b++)
                        wmma::store_matrix_sync(
                            outp + (size_t)(row0 + fr) * 384 + g * HID + 32 * wc + 16 * b,
                            acc[a][b], 384, wmma::mem_row_major);
                }
            }
        }
    }
}

// ---------------- GRU pointwise finish (biases folded in here) ----------------
__global__ void gru_final_kernel(const float* __restrict__ ns,
                                 const float* __restrict__ bih,
                                 const float* __restrict__ bhh,
                                 float* __restrict__ out) {
    int idx = blockIdx.x * blockDim.x + threadIdx.x;
    if (idx >= N_NODES * HID) return;
    int n = idx >> 7;
    int j = idx & 127;
    size_t b = (size_t)n * (3 * HID) + j;
    float ir = g_gi[b] + bih[j],             hr = g_gh[b] + bhh[j];
    float iz = g_gi[b + 128] + bih[j + 128], hz = g_gh[b + 128] + bhh[j + 128];
    float inn = g_gi[b + 256] + bih[j + 256];
    float hn  = g_gh[b + 256] + bhh[j + 256];
    float r = 1.0f / (1.0f + __expf(-(ir + hr)));
    float z = 1.0f / (1.0f + __expf(-(iz + hz)));
    float nn = tanhf(inn + r * hn);
    out[idx] = (1.0f - z) * nn + z * ns[idx];
}

// ---------------- launch ----------------
extern "C" void kernel_launch(void* const* d_in, const int* in_sizes, int n_in,
                              void* d_out, int out_size) {
    const float* ns    = (const float*)d_in[0];
    const void*  eidx  = d_in[1];
    const void*  etype = d_in[2];
    const float* eW    = (const float*)d_in[3];
    const float* eb    = (const float*)d_in[4];
    const float* wih   = (const float*)d_in[5];
    const float* whh   = (const float*)d_in[6];
    const float* bih   = (const float*)d_in[7];
    const float* bhh   = (const float*)d_in[8];
    float* out = (float*)d_out;

    const int GSMEM = (256 * LDAH + 128 * LDAH) * (int)sizeof(__half); // 104448 B
    cudaFuncSetAttribute(wgemm_kernel, cudaFuncAttributeMaxDynamicSharedMemorySize, GSMEM);

    const int SCAN_BLOCKS = (N_NODES + 255) / 256; // 196
    const int GEMM_BLOCKS = (N_NODES + 255) / 256; // 196

    detect_kernel<<<1, 1>>>((const int*)eidx);
    prep_kernel<<<(512 * HID + 255) / 256, 256>>>(eW, wih, whh);
    hist_kernel<<<(N_EDGES + 255) / 256, 256>>>(eidx);
    scan_p1<<<SCAN_BLOCKS, 256>>>();
    scan_p2<<<1, 256>>>(SCAN_BLOCKS);
    scan_p3<<<SCAN_BLOCKS, 256>>>();
    fill_kernel<<<(N_EDGES + 255) / 256, 256>>>(eidx);
    accum_kernel<<<(N_NODES * 32 + 255) / 256, 256>>>(ns, eidx, etype, eb);
    wgemm_kernel<<<dim3(GEMM_BLOCKS, 2), 512, GSMEM>>>(ns, 0);  // mode 0 (agg) + mode 1 (gh)
    wgemm_kernel<<<dim3(GEMM_BLOCKS, 1), 512, GSMEM>>>(ns, 2);  // mode 2 (gi)
    gru_final_kernel<<<(N_NODES * HID + 255) / 256, 256>>>(ns, bih, bhh, out);
}